// round 14
// baseline (speedup 1.0000x reference)
#include <cuda_runtime.h>
#include <cuda_bf16.h>
#include <cstdint>

#define NN 100000
#define EE 600000
#define HH 128
#define AA 64
#define GG 64
#define LL 3
#define EPSN 1e-5f
#define NTILES 782
#define ASTRIDE 264
#define NPW 4
#define NBLK 148
#define CSRB 16               // blocks doing CSR in phase 0
#define GEMB (NBLK - CSRB)    // 132 blocks doing GEMM-L0
#define NODES_PB ((NN + NBLK - 1) / NBLK)   // 676

// ---------------- scratch (device globals) ----------------------------------
__device__ float g_bufA[NN * HH];
__device__ float g_bufB[NN * HH];
__device__ float g_as[NN], g_ad[NN];
__device__ int g_src[EE], g_dst[EE];
__device__ int g_batch[NN];
__device__ int g_deg[NN];
__device__ int g_rowstart[NN + 1];
__device__ int g_cursor[NN];
__device__ int g_ssrc[EE];
__device__ int g_bsum[128];
__device__ float g_colsum[2][HH], g_colsq[2][HH];
__device__ float g_pool[GG * HH];
__device__ unsigned g_barc[12];   // monotonic barrier tickets

__device__ __forceinline__ float lrelu(float x, float a) { return x > 0.f ? x : a * x; }

__device__ __forceinline__ uint32_t smem_u32(const void* p) {
    uint32_t a;
    asm("{ .reg .u64 t; cvta.to.shared.u64 t, %1; cvt.u32.u64 %0, t; }" : "=r"(a) : "l"(p));
    return a;
}
__device__ __forceinline__ void ldm_x4(uint32_t* r, uint32_t addr) {
    asm volatile("ldmatrix.sync.aligned.m8n8.x4.shared.b16 {%0,%1,%2,%3}, [%4];"
                 : "=r"(r[0]), "=r"(r[1]), "=r"(r[2]), "=r"(r[3]) : "r"(addr));
}
__device__ __forceinline__ void mma16816(float* c, const uint32_t* a, const uint32_t* b) {
    asm volatile("mma.sync.aligned.m16n8k16.row.col.f32.bf16.bf16.f32 "
                 "{%0,%1,%2,%3}, {%4,%5,%6,%7}, {%8,%9}, {%0,%1,%2,%3};"
                 : "+f"(c[0]), "+f"(c[1]), "+f"(c[2]), "+f"(c[3])
                 : "r"(a[0]), "r"(a[1]), "r"(a[2]), "r"(a[3]), "r"(b[0]), "r"(b[1]));
}
__device__ __forceinline__ void cpa16(uint32_t dst, const void* src, int sz) {
    asm volatile("cp.async.cg.shared.global [%0], [%1], 16, %2;"
                 :: "r"(dst), "l"(src), "r"(sz) : "memory");
}
#define CPA_COMMIT() asm volatile("cp.async.commit_group;" ::: "memory")
#define CPA_WAIT0()  asm volatile("cp.async.wait_group 0;" ::: "memory")
#define CPA_WAITG1() asm volatile("cp.async.wait_group 1;" ::: "memory")
__device__ __forceinline__ void red4(float* p, float4 v) {
    asm volatile("red.global.add.v4.f32 [%0], {%1,%2,%3,%4};"
                 :: "l"(p), "f"(v.x), "f"(v.y), "f"(v.z), "f"(v.w) : "memory");
}

// ---- software grid barrier: monotonic ticket, graph-replay safe -------------
__device__ __forceinline__ void gbar(int id, unsigned n) {
    __syncthreads();
    __threadfence();
    if (threadIdx.x == 0) {
        unsigned t = atomicAdd(&g_barc[id], 1u);
        unsigned target = t - (t % n) + n;
        unsigned v;
        do { __nanosleep(64); v = *((volatile unsigned*)&g_barc[id]); }
        while ((int)(v - target) < 0);
    }
    __syncthreads();
}

// ---------------- smem layout ------------------------------------------------
#define SA_BYTES  (HH * ASTRIDE * 2)
#define SB_OFF    (2 * SA_BYTES)
#define STAGE_OFF (3 * SA_BYTES)
#define SCR_OFF   (STAGE_OFF + 16384)     // scratch inside stage area (phase-excl)
#define VEC_OFF   (STAGE_OFF + 3 * 8192)
#define SAS_OFF   (VEC_OFF)
#define SAD_OFF   (VEC_OFF + 1024)
#define SAVS_OFF  (VEC_OFF + 2048)
#define SAVD_OFF  (VEC_OFF + 2560)
#define SSH_OFF   (VEC_OFF + 3072)
#define SSC_OFF   (VEC_OFF + 3584)
#define SGB_OFF   (VEC_OFF + 4096)
#define GEMM_SMEM (VEC_OFF + 4608)

// ---------------- GEMM phase helpers ----------------------------------------
__device__ __forceinline__ void prefetch_wave(const float* __restrict__ X, int t0,
                                              int G, int g, uint32_t sbase, int tid) {
    int row0 = (t0 + (g >> 3) * G) << 7;
    int wv = g & 7;
    int nr = NN - row0; if (nr > 128) nr = 128;
    uint32_t stg = sbase + STAGE_OFF + (g % 3) * 8192;
    #pragma unroll
    for (int q = 0; q < 2; q++) {
        int cl = q * 256 + tid;
        int r = wv * 16 + (cl >> 5);
        int k4 = cl & 31;
        int rr = (r < nr) ? r : 0;
        cpa16(stg + cl * 16, ((const float4*)(X + (long long)(row0 + rr) * HH)) + k4,
              (r < nr) ? 16 : 0);
    }
    CPA_COMMIT();
}

__device__ __forceinline__ void convert_wave(char* smem, int dstoff, int g,
                                             int donorm, int tid) {
    const float4* stg = (const float4*)(smem + STAGE_OFF + (g % 3) * 8192);
    int wv = g & 7;
    #pragma unroll
    for (int q = 0; q < 2; q++) {
        int cl = q * 256 + tid;
        int r = wv * 16 + (cl >> 5);
        int k4 = cl & 31;
        float4 v = stg[cl];
        if (donorm) {
            float4 sh = ((const float4*)(smem + SSH_OFF))[k4];
            float4 sc = ((const float4*)(smem + SSC_OFF))[k4];
            float4 bb = ((const float4*)(smem + SGB_OFF))[k4];
            v.x = lrelu((v.x - sh.x) * sc.x + bb.x, 0.01f);
            v.y = lrelu((v.y - sh.y) * sc.y + bb.y, 0.01f);
            v.z = lrelu((v.z - sh.z) * sc.z + bb.z, 0.01f);
            v.w = lrelu((v.w - sh.w) * sc.w + bb.w, 0.01f);
        }
        __nv_bfloat16 h0 = __float2bfloat16_rn(v.x), h1 = __float2bfloat16_rn(v.y);
        __nv_bfloat16 h2 = __float2bfloat16_rn(v.z), h3 = __float2bfloat16_rn(v.w);
        __nv_bfloat162 hp0; hp0.x = h0; hp0.y = h1;
        __nv_bfloat162 hp1; hp1.x = h2; hp1.y = h3;
        __nv_bfloat162 lp0 = __floats2bfloat162_rn(v.x - __bfloat162float(h0),
                                                   v.y - __bfloat162float(h1));
        __nv_bfloat162 lp1 = __floats2bfloat162_rn(v.z - __bfloat162float(h2),
                                                   v.w - __bfloat162float(h3));
        int k0 = k4 << 2;
        uint2 hv = make_uint2(*(unsigned*)&hp0, *(unsigned*)&hp1);
        uint2 lv = make_uint2(*(unsigned*)&lp0, *(unsigned*)&lp1);
        *(uint2*)(smem + dstoff + (r * ASTRIDE + k0) * 2) = hv;
        *(uint2*)(smem + dstoff + (r * ASTRIDE + 128 + k0) * 2) = lv;
    }
}

__device__ void gemm_phase(char* smem, uint32_t sbase, const float* __restrict__ X,
                           const float* __restrict__ Wl,
                           const float* __restrict__ avs, const float* __restrict__ avd,
                           int donorm, int P, int rank) {
    int tid = threadIdx.x;
    int wid = tid >> 5, lane = tid & 31;
    float* sAS = (float*)(smem + SAS_OFF);
    float* sAD = (float*)(smem + SAD_OFF);
    float* sAVS = (float*)(smem + SAVS_OFF);
    float* sAVD = (float*)(smem + SAVD_OFF);

    if (tid < 128) {
        sAVS[tid] = avs[tid];
        sAVD[tid] = avd[tid];
        sAS[tid] = 0.f; sAD[tid] = 0.f;
    }
    // in-kernel W split into sB (Ws is L2-hot; 16K elems)
    {
        __nv_bfloat16* sB = (__nv_bfloat16*)(smem + SB_OFF);
        for (int i = tid; i < HH * HH; i += 256) {
            int k = i >> 7, n = i & 127;
            float w = Wl[i];
            __nv_bfloat16 hi = __float2bfloat16_rn(w);
            __nv_bfloat16 lo = __float2bfloat16_rn(w - __bfloat162float(hi));
            sB[n * ASTRIDE + k] = hi;
            sB[n * ASTRIDE + 128 + k] = lo;
        }
    }

    int ntb = (NTILES - rank + P - 1) / P;
    int gw_total = ntb * 8;

    prefetch_wave(X, rank, P, 0, sbase, tid);
    prefetch_wave(X, rank, P, 1, sbase, tid);
    for (int w = 0; w < 8; w++) {
        if (w + 1 >= gw_total) { CPA_WAIT0(); } else { CPA_WAITG1(); }
        convert_wave(smem, 0, w, donorm, tid);
        if (w + 2 < gw_total) prefetch_wave(X, rank, P, w + 2, sbase, tid);
    }
    __syncthreads();

    int m0 = (wid >> 1) << 5;
    int n0 = (wid & 1) << 6;
    int arow = m0 + (lane & 7) + ((lane >> 3) & 1) * 8;
    uint32_t aBase = sbase + (arow * ASTRIDE + ((lane >> 4) & 1) * 8) * 2;
    int brow = n0 + (lane & 7) + ((lane >> 4) & 1) * 8;
    uint32_t bAddr = sbase + SB_OFF + (brow * ASTRIDE + ((lane >> 3) & 1) * 8) * 2;
    int qrow = lane >> 2;
    int qcol = (lane & 3) << 1;

    int p = 0;
    for (int i = 0; ; i++) {
        int t = rank + i * P;
        int row0 = t << 7;
        int nrows = NN - row0; if (nrows > 128) nrows = 128;
        int have_next = (i + 1 < ntb);
        uint32_t aAddr = aBase + p * SA_BYTES;
        int dstoff = (p ^ 1) * SA_BYTES;
        float* sASp = sAS + p * 128;
        float* sADp = sAD + p * 128;

        float acc[2][8][4];
        #pragma unroll
        for (int mb = 0; mb < 2; mb++)
            #pragma unroll
            for (int nb = 0; nb < 8; nb++)
                #pragma unroll
                for (int j = 0; j < 4; j++) acc[mb][nb][j] = 0.f;

        for (int w = 0; w < 8; w++) {
            if (have_next) {
                int g = (i + 1) * 8 + w;
                if (g + 1 >= gw_total) { CPA_WAIT0(); } else { CPA_WAITG1(); }
                convert_wave(smem, dstoff, g, donorm, tid);
                if (g + 2 < gw_total) prefetch_wave(X, rank, P, g + 2, sbase, tid);
                if (w == 0 && tid < 128) {
                    sAS[(p ^ 1) * 128 + tid] = 0.f;
                    sAD[(p ^ 1) * 128 + tid] = 0.f;
                }
            }
            int kofs = w * 16;
            uint32_t ah[2][4], al[2][4];
            ldm_x4(ah[0], aAddr + kofs * 2);
            ldm_x4(ah[1], aAddr + kofs * 2 + 16 * ASTRIDE * 2);
            ldm_x4(al[0], aAddr + (kofs + 128) * 2);
            ldm_x4(al[1], aAddr + (kofs + 128) * 2 + 16 * ASTRIDE * 2);
            #pragma unroll
            for (int nbp = 0; nbp < 4; nbp++) {
                uint32_t bh[4], bl[4];
                ldm_x4(bh, bAddr + kofs * 2 + nbp * 16 * ASTRIDE * 2);
                ldm_x4(bl, bAddr + (kofs + 128) * 2 + nbp * 16 * ASTRIDE * 2);
                #pragma unroll
                for (int mb = 0; mb < 2; mb++) {
                    mma16816(acc[mb][2 * nbp],     ah[mb], &bh[0]);
                    mma16816(acc[mb][2 * nbp + 1], ah[mb], &bh[2]);
                    mma16816(acc[mb][2 * nbp],     al[mb], &bh[0]);
                    mma16816(acc[mb][2 * nbp + 1], al[mb], &bh[2]);
                    mma16816(acc[mb][2 * nbp],     ah[mb], &bl[0]);
                    mma16816(acc[mb][2 * nbp + 1], ah[mb], &bl[2]);
                }
            }
        }
        __syncthreads();

        #pragma unroll
        for (int mb = 0; mb < 2; mb++) {
            int rlo = m0 + mb * 16 + qrow;
            int rhi = rlo + 8;
            float as_lo = 0.f, ad_lo = 0.f, as_hi = 0.f, ad_hi = 0.f;
            #pragma unroll
            for (int nb = 0; nb < 8; nb++) {
                int col = n0 + nb * 8 + qcol;
                float c0 = acc[mb][nb][0], c1 = acc[mb][nb][1];
                float c2 = acc[mb][nb][2], c3 = acc[mb][nb][3];
                float s0 = sAVS[col], s1 = sAVS[col + 1];
                float d0 = sAVD[col], d1 = sAVD[col + 1];
                as_lo += c0 * s0 + c1 * s1;  ad_lo += c0 * d0 + c1 * d1;
                as_hi += c2 * s0 + c3 * s1;  ad_hi += c2 * d0 + c3 * d1;
                if (rlo < nrows) {
                    float2* pp = (float2*)(g_bufA + (long long)(row0 + rlo) * HH + col);
                    *pp = make_float2(c0, c1);
                }
                if (rhi < nrows) {
                    float2* pp = (float2*)(g_bufA + (long long)(row0 + rhi) * HH + col);
                    *pp = make_float2(c2, c3);
                }
            }
            #pragma unroll
            for (int o = 1; o < 4; o <<= 1) {
                as_lo += __shfl_xor_sync(0xFFFFFFFFu, as_lo, o);
                ad_lo += __shfl_xor_sync(0xFFFFFFFFu, ad_lo, o);
                as_hi += __shfl_xor_sync(0xFFFFFFFFu, as_hi, o);
                ad_hi += __shfl_xor_sync(0xFFFFFFFFu, ad_hi, o);
            }
            if ((lane & 3) == 0) {
                atomicAdd(&sASp[rlo], as_lo); atomicAdd(&sADp[rlo], ad_lo);
                atomicAdd(&sASp[rhi], as_hi); atomicAdd(&sADp[rhi], ad_hi);
            }
        }
        __syncthreads();
        if (tid < nrows) {
            int r = row0 + tid;
            g_as[r] = sASp[tid]; g_ad[r] = sADp[tid];
        }
        if (!have_next) break;
        p ^= 1;
    }
}

// ---------------- agg phase --------------------------------------------------
__device__ void agg_phase(char* smem, const float* __restrict__ bias, int mode,
                          float* slotsum, float* slotsq) {
    int tid = threadIdx.x;
    int wid = tid >> 5, lane = tid & 31;
    float* s_sum = (float*)(smem + STAGE_OFF);
    float* s_sq  = (float*)(smem + STAGE_OFF + 512);
    int2 (*s_sa)[NPW][32] = (int2(*)[NPW][32])(smem + STAGE_OFF + 1024);
    if (mode == 1 && tid < HH) { s_sum[tid] = 0.f; s_sq[tid] = 0.f; }
    __syncthreads();

    int start = blockIdx.x * NODES_PB;
    int end = start + NODES_PB; if (end > NN) end = NN;
    float4 bb = ((const float4*)bias)[lane];
    float4 cs = make_float4(0.f, 0.f, 0.f, 0.f);
    float4 cq = make_float4(0.f, 0.f, 0.f, 0.f);
    float4 pacc = make_float4(0.f, 0.f, 0.f, 0.f);
    int curb = -1;

    for (int nb = start + wid * NPW; nb < end; nb += 8 * NPW) {
        int degs[NPW], rss[NPW], fd[NPW];
        float adv[NPW];
        #pragma unroll
        for (int n = 0; n < NPW; n++) {
            int node = nb + n;
            int val = node < end;
            rss[n] = val ? g_rowstart[node] : 0;
            int re = val ? g_rowstart[node + 1] : 0;
            degs[n] = re - rss[n];
            adv[n] = val ? __ldcg(&g_ad[node]) : 0.f;
            fd[n] = (degs[n] <= 32) ? degs[n] : 0;
        }
        int msrc[NPW];
        float exv[NPW];
        #pragma unroll
        for (int n = 0; n < NPW; n++)
            msrc[n] = (lane < fd[n]) ? g_ssrc[rss[n] + lane] : 0;
        #pragma unroll
        for (int n = 0; n < NPW; n++)
            exv[n] = (lane < fd[n])
                   ? __expf(lrelu(__ldcg(&g_as[msrc[n]]) + adv[n], 0.2f)) : 0.f;
        float sv[NPW];
        #pragma unroll
        for (int n = 0; n < NPW; n++) sv[n] = exv[n];
        #pragma unroll
        for (int o = 16; o; o >>= 1) {
            #pragma unroll
            for (int n = 0; n < NPW; n++)
                sv[n] += __shfl_xor_sync(0xFFFFFFFFu, sv[n], o);
        }
        #pragma unroll
        for (int n = 0; n < NPW; n++)
            s_sa[wid][n][lane] = make_int2(msrc[n],
                                           __float_as_int(exv[n] / (sv[n] + 1e-16f)));
        __syncwarp();

        float4 acc[NPW];
        #pragma unroll
        for (int n = 0; n < NPW; n++) acc[n] = bb;
        int dmax = 0;
        #pragma unroll
        for (int n = 0; n < NPW; n++) dmax = max(dmax, fd[n]);
        for (int j = 0; j < dmax; j++) {
            #pragma unroll
            for (int n = 0; n < NPW; n++) {
                if (j < fd[n]) {
                    int2 sa = s_sa[wid][n][j];
                    float al = __int_as_float(sa.y);
                    float4 v = __ldcg(((const float4*)(g_bufA + (long long)sa.x * HH)) + lane);
                    acc[n].x += al * v.x; acc[n].y += al * v.y;
                    acc[n].z += al * v.z; acc[n].w += al * v.w;
                }
            }
        }
        __syncwarp();
        #pragma unroll
        for (int n = 0; n < NPW; n++) {
            if (degs[n] > 32) {
                int rs = rss[n], re = rss[n] + degs[n];
                float m = -1e30f, s = 0.f;
                for (int i = rs + lane; i < re; i += 32) {
                    int src = g_ssrc[i];
                    float x = lrelu(__ldcg(&g_as[src]) + adv[n], 0.2f);
                    if (x > m) { s = s * __expf(m - x) + 1.f; m = x; }
                    else       { s += __expf(x - m); }
                }
                #pragma unroll
                for (int o = 16; o; o >>= 1) {
                    float om = __shfl_xor_sync(0xFFFFFFFFu, m, o);
                    float os = __shfl_xor_sync(0xFFFFFFFFu, s, o);
                    float nm = fmaxf(m, om);
                    s = s * __expf(m - nm) + os * __expf(om - nm);
                    m = nm;
                }
                float inv = 1.f / (s + 1e-16f);
                for (int i = rs; i < re; ++i) {
                    int src = g_ssrc[i];
                    float alpha = __expf(lrelu(__ldcg(&g_as[src]) + adv[n], 0.2f) - m) * inv;
                    float4 v = __ldcg(((const float4*)(g_bufA + (long long)src * HH)) + lane);
                    acc[n].x += alpha * v.x; acc[n].y += alpha * v.y;
                    acc[n].z += alpha * v.z; acc[n].w += alpha * v.w;
                }
            }
        }

        #pragma unroll
        for (int n = 0; n < NPW; n++) {
            int node = nb + n;
            if (node >= end) break;
            float4 a = acc[n];
            if (mode == 2) {
                int b = g_batch[node];
                if (b != curb) {
                    if (curb >= 0) red4(&g_pool[curb * HH + (lane << 2)], pacc);
                    curb = b;
                    pacc = make_float4(0.f, 0.f, 0.f, 0.f);
                }
                pacc.x += a.x; pacc.y += a.y; pacc.z += a.z; pacc.w += a.w;
            } else {
                ((float4*)(g_bufB + (long long)node * HH))[lane] = a;
                if (mode == 1) {
                    cs.x += a.x; cs.y += a.y; cs.z += a.z; cs.w += a.w;
                    cq.x += a.x * a.x; cq.y += a.y * a.y;
                    cq.z += a.z * a.z; cq.w += a.w * a.w;
                }
            }
        }
    }

    if (mode == 2) {
        if (curb >= 0) red4(&g_pool[curb * HH + (lane << 2)], pacc);
    } else if (mode == 1) {
        int c0 = lane << 2;
        atomicAdd(&s_sum[c0],     cs.x); atomicAdd(&s_sum[c0 + 1], cs.y);
        atomicAdd(&s_sum[c0 + 2], cs.z); atomicAdd(&s_sum[c0 + 3], cs.w);
        atomicAdd(&s_sq[c0],      cq.x); atomicAdd(&s_sq[c0 + 1],  cq.y);
        atomicAdd(&s_sq[c0 + 2],  cq.z); atomicAdd(&s_sq[c0 + 3],  cq.w);
        __syncthreads();
        if (tid < HH) {
            atomicAdd(&slotsum[tid], s_sum[tid]);
            atomicAdd(&slotsq[tid], s_sq[tid]);
        }
    }
}

// ---------------- norm factors (per block, redundant) ------------------------
__device__ void compute_norm(char* smem, const float* __restrict__ w,
                             const float* __restrict__ b, const float* __restrict__ ms,
                             const float* slotsum, const float* slotsq) {
    int tid = threadIdx.x;
    if (tid < HH) {
        float invN = 1.0f / (float)NN;
        float mean = __ldcg(&slotsum[tid]) * invN;
        float ex2 = __ldcg(&slotsq[tid]) * invN;
        float s = ms[tid];
        float var = ex2 - 2.f * s * mean * mean + s * s * mean * mean;
        ((float*)(smem + SSH_OFF))[tid] = mean * s;
        ((float*)(smem + SSC_OFF))[tid] = w[tid] * rsqrtf(var + EPSN);
        ((float*)(smem + SGB_OFF))[tid] = b[tid];
    }
    __syncthreads();
}

// ---------------- CSR phase (CSRB blocks) ------------------------------------
__device__ void scan_chunk(char* smem, int c) {
    int* s_w = (int*)(smem + SCR_OFF);
    int t = threadIdx.x;
    int base = c * 1024 + t * 4;
    int d[4];
    #pragma unroll
    for (int i = 0; i < 4; i++) d[i] = (base + i < NN) ? g_deg[base + i] : 0;
    int local = d[0] + d[1] + d[2] + d[3];
    int lane = t & 31, w = t >> 5;
    int v = local;
    #pragma unroll
    for (int o = 1; o < 32; o <<= 1) {
        int u = __shfl_up_sync(0xFFFFFFFFu, v, o);
        if (lane >= o) v += u;
    }
    if (lane == 31) s_w[w] = v;
    __syncthreads();
    if (t < 8) {
        int x = s_w[t];
        #pragma unroll
        for (int o = 1; o < 8; o <<= 1) {
            int u = __shfl_up_sync(0xFFu, x, o);
            if (t >= o) x += u;
        }
        s_w[t] = x;
    }
    __syncthreads();
    int warpoff = (w > 0) ? s_w[w - 1] : 0;
    int excl = warpoff + v - local;
    #pragma unroll
    for (int i = 0; i < 4; i++) {
        if (base + i < NN) g_rowstart[base + i] = excl;
        excl += d[i];
    }
    if (t == 0) g_bsum[c] = s_w[7];
    __syncthreads();
}

__device__ void csr_phase(char* smem, int rk, const void* eraw, const void* braw) {
    int tid = threadIdx.x;
    int* s_flag = (int*)(smem + SCR_OFF + 64);
    if (tid == 0) { s_flag[0] = 0; s_flag[1] = 0; }
    __syncthreads();
    if (tid < 64) {
        long long v = ((const long long*)eraw)[(long long)tid * (EE / 64)];
        if (v < 0 || v >= NN) atomicOr(&s_flag[0], 1);
    } else if (tid < 128) {
        long long bv = ((const long long*)braw)[(long long)(tid - 64) * ((NN / 2) / 64)];
        if (bv < 0 || bv >= GG) atomicOr(&s_flag[1], 1);
    }
    __syncthreads();
    int e32 = s_flag[0], b32 = s_flag[1];

    // cvt + hist (strided over CSRB blocks)
    for (int i = rk * 256 + tid; i < EE; i += CSRB * 256) {
        int s, d;
        if (e32) {
            const int* p = (const int*)eraw;
            s = p[i]; d = p[EE + i];
        } else {
            const long long* p = (const long long*)eraw;
            s = (int)p[i]; d = (int)p[EE + i];
        }
        g_src[i] = s; g_dst[i] = d;
        atomicAdd(&g_deg[d], 1);
    }
    for (int i = rk * 256 + tid; i < NN; i += CSRB * 256) {
        if (b32) g_batch[i] = ((const int*)braw)[i];
        else     g_batch[i] = (int)((const long long*)braw)[i];
    }
    for (int i = rk * 256 + tid; i < GG * HH; i += CSRB * 256) g_pool[i] = 0.f;
    if (rk == 0 && tid < 128) {
        g_colsum[0][tid] = 0.f; g_colsum[1][tid] = 0.f;
        g_colsq[0][tid] = 0.f;  g_colsq[1][tid] = 0.f;
    }
    gbar(6, CSRB);

    // scan level 1
    const int NCH = (NN + 1023) / 1024;   // 98
    for (int c = rk; c < NCH; c += CSRB) scan_chunk(smem, c);
    gbar(7, CSRB);

    // scan level 2 + apply (each block scans the 98 sums redundantly)
    {
        int* sb = (int*)(smem + SCR_OFF + 128);
        int t = tid;
        if (t < 128) sb[t] = (t < NCH) ? g_bsum[t] : 0;
        __syncthreads();
        for (int o = 1; o < 128; o <<= 1) {
            int u = (t < 128 && t >= o) ? sb[t - o] : 0;
            __syncthreads();
            if (t < 128) sb[t] += u;
            __syncthreads();
        }
        for (int i = rk * 256 + tid; i < NN; i += CSRB * 256) {
            int blk = i >> 10;
            int off = (blk > 0) ? sb[blk - 1] : 0;
            int v = g_rowstart[i] + off;
            g_rowstart[i] = v;
            g_cursor[i] = v;
            g_deg[i] = 0;
        }
        if (rk == 0 && tid == 0) g_rowstart[NN] = EE;
    }
    gbar(8, CSRB);

    // fill
    for (int e = rk * 256 + tid; e < EE; e += CSRB * 256) {
        int d = g_dst[e];
        int slot = atomicAdd(&g_cursor[d], 1);
        g_ssrc[slot] = g_src[e];
    }
}

// ---------------- THE mega kernel --------------------------------------------
__global__ void __launch_bounds__(256, 1)
k_mega(const float* __restrict__ x, const void* eraw, const void* braw,
       const float* __restrict__ Ws,
       const float* __restrict__ att_src, const float* __restrict__ att_dst,
       const float* __restrict__ conv_bias,
       const float* __restrict__ gn_w, const float* __restrict__ gn_b,
       const float* __restrict__ gn_ms,
       const float* __restrict__ W1, const float* __restrict__ b1,
       const float* __restrict__ W2, const float* __restrict__ b2,
       float* __restrict__ out) {
    extern __shared__ char smem[];
    uint32_t sbase = smem_u32(smem);
    int bid = blockIdx.x;
    int tid = threadIdx.x;

    // ---- phase 0: CSR (blocks GEMB..) || GEMM-L0 (blocks 0..GEMB-1) ----
    if (bid < GEMB) {
        gemm_phase(smem, sbase, x, Ws, att_src, att_dst, 0, GEMB, bid);
    } else {
        csr_phase(smem, bid - GEMB, eraw, braw);
    }
    gbar(0, NBLK);

    // ---- L0 agg (+stats slot 0) ----
    agg_phase(smem, conv_bias, 1, g_colsum[0], g_colsq[0]);
    gbar(1, NBLK);

    // ---- L1 ----
    compute_norm(smem, gn_w, gn_b, gn_ms, g_colsum[0], g_colsq[0]);
    gemm_phase(smem, sbase, g_bufB, Ws + HH * HH, att_src + HH, att_dst + HH, 1, NBLK, bid);
    gbar(2, NBLK);
    agg_phase(smem, conv_bias + HH, 1, g_colsum[1], g_colsq[1]);
    gbar(3, NBLK);

    // ---- L2 ----
    compute_norm(smem, gn_w + HH, gn_b + HH, gn_ms + HH, g_colsum[1], g_colsq[1]);
    gemm_phase(smem, sbase, g_bufB, Ws + 2 * HH * HH, att_src + 2 * HH, att_dst + 2 * HH,
               1, NBLK, bid);
    gbar(4, NBLK);
    agg_phase(smem, conv_bias + 2 * HH, 2, g_colsum[0], g_colsq[0]);
    gbar(5, NBLK);

    // ---- MLP: blocks 0..GG-1, one graph each ----
    if (bid < GG) {
        float* sp = (float*)(smem + STAGE_OFF);
        float* sz = (float*)(smem + STAGE_OFF + 512);
        int g = bid, c = tid;
        if (c < HH) sp[c] = __ldcg(&g_pool[g * HH + c]);
        __syncthreads();
        if (c < HH) {
            float a1 = b1[c];
            #pragma unroll 4
            for (int k = 0; k < HH; k++) a1 += sp[k] * W1[k * HH + c];
            sz[c] = lrelu(a1, 0.01f);
        }
        __syncthreads();
        if (c < AA) {
            float a2 = b2[c];
            #pragma unroll 4
            for (int k = 0; k < HH; k++) a2 += sz[k] * W2[k * AA + c];
            out[g * AA + c] = a2;
        }
    }
}

// ---------------- launcher ---------------------------------------------------
extern "C" void kernel_launch(void* const* d_in, const int* in_sizes, int n_in,
                              void* d_out, int out_size) {
    const float* x        = (const float*)d_in[0];
    const void*  e_raw    = d_in[1];
    const void*  b_raw    = d_in[2];
    const float* Ws       = (const float*)d_in[3];
    const float* att_src  = (const float*)d_in[4];
    const float* att_dst  = (const float*)d_in[5];
    const float* conv_bias= (const float*)d_in[6];
    const float* gn_w     = (const float*)d_in[7];
    const float* gn_b     = (const float*)d_in[8];
    const float* gn_ms    = (const float*)d_in[9];
    const float* W1       = (const float*)d_in[10];
    const float* b1       = (const float*)d_in[11];
    const float* W2       = (const float*)d_in[12];
    const float* b2       = (const float*)d_in[13];

    cudaFuncSetAttribute(k_mega, cudaFuncAttributeMaxDynamicSharedMemorySize, GEMM_SMEM);
    k_mega<<<NBLK, 256, GEMM_SMEM>>>(x, e_raw, b_raw, Ws, att_src, att_dst, conv_bias,
                                     gn_w, gn_b, gn_ms, W1, b1, W2, b2, (float*)d_out);
}

// round 15
// speedup vs baseline: 1.9605x; 1.9605x over previous
#include <cuda_runtime.h>
#include <cuda_bf16.h>
#include <cstdint>

#define NN 100000
#define EE 600000
#define HH 128
#define AA 64
#define GG 64
#define LL 3
#define EPSN 1e-5f
#define NTILES 782
#define ASTRIDE 264
#define IMG_ELEMS (HH * ASTRIDE)
#define NPW 4

// ---------------- scratch (device globals) ----------------------------------
__device__ float g_bufA[NN * HH];
__device__ float g_bufB[NN * HH];
__device__ float g_as[NN], g_ad[NN];
__device__ int g_src[EE], g_dst[EE];
__device__ int g_batch[NN];
__device__ int g_deg[NN];
__device__ int g_rowstart[NN + 1];
__device__ int g_cursor[NN];
__device__ int g_ssrc[EE];
__device__ int g_bsum[128];
__device__ float g_colsum[2][HH], g_colsq[2][HH];
__device__ float g_pool[GG * HH];
__device__ __align__(16) __nv_bfloat16 g_Wimg[LL * IMG_ELEMS];

__device__ __forceinline__ float lrelu(float x, float a) { return x > 0.f ? x : a * x; }

__device__ __forceinline__ uint32_t smem_u32(const void* p) {
    uint32_t a;
    asm("{ .reg .u64 t; cvta.to.shared.u64 t, %1; cvt.u32.u64 %0, t; }" : "=r"(a) : "l"(p));
    return a;
}
__device__ __forceinline__ void ldm_x4(uint32_t* r, uint32_t addr) {
    asm volatile("ldmatrix.sync.aligned.m8n8.x4.shared.b16 {%0,%1,%2,%3}, [%4];"
                 : "=r"(r[0]), "=r"(r[1]), "=r"(r[2]), "=r"(r[3]) : "r"(addr));
}
__device__ __forceinline__ void mma16816(float* c, const uint32_t* a, const uint32_t* b) {
    asm volatile("mma.sync.aligned.m16n8k16.row.col.f32.bf16.bf16.f32 "
                 "{%0,%1,%2,%3}, {%4,%5,%6,%7}, {%8,%9}, {%0,%1,%2,%3};"
                 : "+f"(c[0]), "+f"(c[1]), "+f"(c[2]), "+f"(c[3])
                 : "r"(a[0]), "r"(a[1]), "r"(a[2]), "r"(a[3]), "r"(b[0]), "r"(b[1]));
}
__device__ __forceinline__ void cpa16(uint32_t dst, const void* src, int sz) {
    asm volatile("cp.async.cg.shared.global [%0], [%1], 16, %2;"
                 :: "r"(dst), "l"(src), "r"(sz) : "memory");
}
#define CPA_COMMIT() asm volatile("cp.async.commit_group;" ::: "memory")
#define CPA_WAIT0()  asm volatile("cp.async.wait_group 0;" ::: "memory")
#define CPA_WAITG1() asm volatile("cp.async.wait_group 1;" ::: "memory")
__device__ __forceinline__ void red4(float* p, float4 v) {
    asm volatile("red.global.add.v4.f32 [%0], {%1,%2,%3,%4};"
                 :: "l"(p), "f"(v.x), "f"(v.y), "f"(v.z), "f"(v.w) : "memory");
}

// ---------------- cvt + inline dtype detection + histogram -------------------
__global__ void k_cvt(const void* eraw, const void* braw) {
    __shared__ int s_e32, s_b32;
    int tid = threadIdx.x;
    if (tid == 0) { s_e32 = 0; s_b32 = 0; }
    __syncthreads();
    if (tid < 64) {
        long long v = ((const long long*)eraw)[(long long)tid * (EE / 64)];
        if (v < 0 || v >= NN) atomicOr(&s_e32, 1);
    } else if (tid < 128) {
        long long bv = ((const long long*)braw)[(long long)(tid - 64) * ((NN / 2) / 64)];
        if (bv < 0 || bv >= GG) atomicOr(&s_b32, 1);
    }
    __syncthreads();
    int e32 = s_e32, b32 = s_b32;
    int i = blockIdx.x * blockDim.x + tid;
    if (i < EE) {
        int s, d;
        if (e32) {
            const int* p = (const int*)eraw;
            s = p[i]; d = p[EE + i];
        } else {
            const long long* p = (const long long*)eraw;
            s = (int)p[i]; d = (int)p[EE + i];
        }
        g_src[i] = s; g_dst[i] = d;
        atomicAdd(&g_deg[d], 1);
    }
    if (i < NN) {
        if (b32) g_batch[i] = ((const int*)braw)[i];
        else     g_batch[i] = (int)((const long long*)braw)[i];
    }
    if (i < GG * HH) g_pool[i] = 0.f;
    if (i < HH) {      // re-arm stat slots every replay
        g_colsum[0][i] = 0.f; g_colsum[1][i] = 0.f;
        g_colsq[0][i] = 0.f;  g_colsq[1][i] = 0.f;
    }
}

// ---------------- W prep ----------------------------------------------------
__global__ void k_prepW(const float* __restrict__ Ws) {
    int i = blockIdx.x * blockDim.x + threadIdx.x;
    if (i >= LL * HH * HH) return;
    int l = i / (HH * HH);
    int r = i - l * HH * HH;
    int k = r >> 7;
    int n = r & 127;
    float w = Ws[i];
    __nv_bfloat16 hi = __float2bfloat16_rn(w);
    float resid = w - __bfloat162float(hi);
    __nv_bfloat16 lo = __float2bfloat16_rn(resid);
    __nv_bfloat16* img = g_Wimg + (long long)l * IMG_ELEMS;
    img[n * ASTRIDE + k] = hi;
    img[n * ASTRIDE + 128 + k] = lo;
}

// ---------------- CSR build -------------------------------------------------
__global__ void k_scan1() {
    __shared__ int s_w[8];
    int b = blockIdx.x, t = threadIdx.x;
    int base = b * 1024 + t * 4;
    int d[4];
    #pragma unroll
    for (int i = 0; i < 4; i++) d[i] = (base + i < NN) ? g_deg[base + i] : 0;
    int local = d[0] + d[1] + d[2] + d[3];
    int lane = t & 31, w = t >> 5;
    int v = local;
    #pragma unroll
    for (int o = 1; o < 32; o <<= 1) {
        int u = __shfl_up_sync(0xFFFFFFFFu, v, o);
        if (lane >= o) v += u;
    }
    if (lane == 31) s_w[w] = v;
    __syncthreads();
    if (t < 8) {
        int x = s_w[t];
        #pragma unroll
        for (int o = 1; o < 8; o <<= 1) {
            int u = __shfl_up_sync(0xFFu, x, o);
            if (t >= o) x += u;
        }
        s_w[t] = x;
    }
    __syncthreads();
    int warpoff = (w > 0) ? s_w[w - 1] : 0;
    int excl = warpoff + v - local;
    #pragma unroll
    for (int i = 0; i < 4; i++) {
        if (base + i < NN) g_rowstart[base + i] = excl;
        excl += d[i];
    }
    if (t == 0) g_bsum[b] = s_w[7];
}

__global__ void k_scan23() {
    __shared__ int sb[128];
    int t = threadIdx.x;
    int NB = (NN + 1023) / 1024;
    if (t < 128) sb[t] = (t < NB) ? g_bsum[t] : 0;
    __syncthreads();
    for (int o = 1; o < 128; o <<= 1) {
        int u = (t < 128 && t >= o) ? sb[t - o] : 0;
        __syncthreads();
        if (t < 128) sb[t] += u;
        __syncthreads();
    }
    int i = blockIdx.x * blockDim.x + t;
    if (i < NN) {
        int blk = i >> 10;
        int off = (blk > 0) ? sb[blk - 1] : 0;
        int v = g_rowstart[i] + off;
        g_rowstart[i] = v;
        g_cursor[i] = v;
        g_deg[i] = 0;
    }
    if (i == 0) g_rowstart[NN] = EE;
}

__global__ void k_fill() {
    int e = blockIdx.x * blockDim.x + threadIdx.x;
    if (e >= EE) return;
    int d = g_dst[e];
    int slot = atomicAdd(&g_cursor[d], 1);
    g_ssrc[slot] = g_src[e];
}

// ---------------- HMMA GEMM: persistent, wave-pipelined convert --------------
#define SA_BYTES  (HH * ASTRIDE * 2)
#define SB_OFF    (2 * SA_BYTES)
#define STAGE_OFF (3 * SA_BYTES)
#define VEC_OFF   (STAGE_OFF + 3 * 8192)
#define SAS_OFF   (VEC_OFF)
#define SAD_OFF   (VEC_OFF + 1024)
#define SAVS_OFF  (VEC_OFF + 2048)
#define SAVD_OFF  (VEC_OFF + 2560)
#define SSH_OFF   (VEC_OFF + 3072)
#define SSC_OFF   (VEC_OFF + 3584)
#define SGB_OFF   (VEC_OFF + 4096)
#define GEMM_SMEM (VEC_OFF + 4608)

__device__ __forceinline__ void prefetch_wave(const float* __restrict__ X, int t0,
                                              int G, int g, uint32_t sbase, int tid) {
    int row0 = (t0 + (g >> 3) * G) << 7;
    int wv = g & 7;
    int nr = NN - row0; if (nr > 128) nr = 128;
    uint32_t stg = sbase + STAGE_OFF + (g % 3) * 8192;
    #pragma unroll
    for (int q = 0; q < 2; q++) {
        int cl = q * 256 + tid;
        int r = wv * 16 + (cl >> 5);
        int k4 = cl & 31;
        int rr = (r < nr) ? r : 0;
        cpa16(stg + cl * 16, ((const float4*)(X + (long long)(row0 + rr) * HH)) + k4,
              (r < nr) ? 16 : 0);
    }
    CPA_COMMIT();
}

__device__ __forceinline__ void convert_wave(char* smem, int dstoff, int g,
                                             int donorm, int tid) {
    const float4* stg = (const float4*)(smem + STAGE_OFF + (g % 3) * 8192);
    int wv = g & 7;
    #pragma unroll
    for (int q = 0; q < 2; q++) {
        int cl = q * 256 + tid;
        int r = wv * 16 + (cl >> 5);
        int k4 = cl & 31;
        float4 v = stg[cl];
        if (donorm) {
            float4 sh = ((const float4*)(smem + SSH_OFF))[k4];
            float4 sc = ((const float4*)(smem + SSC_OFF))[k4];
            float4 bb = ((const float4*)(smem + SGB_OFF))[k4];
            v.x = lrelu((v.x - sh.x) * sc.x + bb.x, 0.01f);
            v.y = lrelu((v.y - sh.y) * sc.y + bb.y, 0.01f);
            v.z = lrelu((v.z - sh.z) * sc.z + bb.z, 0.01f);
            v.w = lrelu((v.w - sh.w) * sc.w + bb.w, 0.01f);
        }
        __nv_bfloat16 h0 = __float2bfloat16_rn(v.x), h1 = __float2bfloat16_rn(v.y);
        __nv_bfloat16 h2 = __float2bfloat16_rn(v.z), h3 = __float2bfloat16_rn(v.w);
        __nv_bfloat162 hp0; hp0.x = h0; hp0.y = h1;
        __nv_bfloat162 hp1; hp1.x = h2; hp1.y = h3;
        __nv_bfloat162 lp0 = __floats2bfloat162_rn(v.x - __bfloat162float(h0),
                                                   v.y - __bfloat162float(h1));
        __nv_bfloat162 lp1 = __floats2bfloat162_rn(v.z - __bfloat162float(h2),
                                                   v.w - __bfloat162float(h3));
        int k0 = k4 << 2;
        uint2 hv = make_uint2(*(unsigned*)&hp0, *(unsigned*)&hp1);
        uint2 lv = make_uint2(*(unsigned*)&lp0, *(unsigned*)&lp1);
        *(uint2*)(smem + dstoff + (r * ASTRIDE + k0) * 2) = hv;
        *(uint2*)(smem + dstoff + (r * ASTRIDE + 128 + k0) * 2) = lv;
    }
}

__global__ void __launch_bounds__(256, 1)
k_gemm_mma(const float* __restrict__ X, int layer, float* __restrict__ Y,
           const float* __restrict__ avs, const float* __restrict__ avd,
           int donorm, int slot,
           const float* __restrict__ gnw, const float* __restrict__ gnb,
           const float* __restrict__ gnms) {
    extern __shared__ char smem[];
    uint32_t sbase = smem_u32(smem);
    int tid = threadIdx.x;
    int wid = tid >> 5, lane = tid & 31;
    int G = gridDim.x;
    int t0 = blockIdx.x;
    int ntb = (NTILES - t0 + G - 1) / G;
    int gw_total = ntb * 8;

    float* sAS = (float*)(smem + SAS_OFF);
    float* sAD = (float*)(smem + SAD_OFF);
    float* sAVS = (float*)(smem + SAVS_OFF);
    float* sAVD = (float*)(smem + SAVD_OFF);

    if (tid < 128) {
        sAVS[tid] = avs[tid];
        sAVD[tid] = avd[tid];
        sAS[tid] = 0.f; sAD[tid] = 0.f;
        if (donorm) {     // per-block norm factors from global stat accumulators
            float invN = 1.0f / (float)NN;
            float mean = __ldcg(&g_colsum[slot][tid]) * invN;
            float ex2 = __ldcg(&g_colsq[slot][tid]) * invN;
            float s = gnms[tid];
            float var = ex2 - 2.f * s * mean * mean + s * s * mean * mean;
            ((float*)(smem + SSH_OFF))[tid] = mean * s;
            ((float*)(smem + SSC_OFF))[tid] = gnw[tid] * rsqrtf(var + EPSN);
            ((float*)(smem + SGB_OFF))[tid] = gnb[tid];
        }
    }
    {
        const float4* src = (const float4*)(g_Wimg + (long long)layer * IMG_ELEMS);
        float4* dst = (float4*)(smem + SB_OFF);
        for (int i = tid; i < 4224; i += 256) dst[i] = src[i];
    }
    __syncthreads();

    prefetch_wave(X, t0, G, 0, sbase, tid);
    prefetch_wave(X, t0, G, 1, sbase, tid);
    for (int w = 0; w < 8; w++) {
        if (w + 1 >= gw_total) { CPA_WAIT0(); } else { CPA_WAITG1(); }
        convert_wave(smem, 0, w, donorm, tid);
        if (w + 2 < gw_total) prefetch_wave(X, t0, G, w + 2, sbase, tid);
    }
    __syncthreads();

    int m0 = (wid >> 1) << 5;
    int n0 = (wid & 1) << 6;
    int arow = m0 + (lane & 7) + ((lane >> 3) & 1) * 8;
    uint32_t aBase = sbase + (arow * ASTRIDE + ((lane >> 4) & 1) * 8) * 2;
    int brow = n0 + (lane & 7) + ((lane >> 4) & 1) * 8;
    uint32_t bAddr = sbase + SB_OFF + (brow * ASTRIDE + ((lane >> 3) & 1) * 8) * 2;
    int qrow = lane >> 2;
    int qcol = (lane & 3) << 1;

    int p = 0;
    for (int i = 0; ; i++) {
        int t = t0 + i * G;
        int row0 = t << 7;
        int nrows = NN - row0; if (nrows > 128) nrows = 128;
        int have_next = (i + 1 < ntb);
        uint32_t aAddr = aBase + p * SA_BYTES;
        int dstoff = (p ^ 1) * SA_BYTES;
        float* sASp = sAS + p * 128;
        float* sADp = sAD + p * 128;

        float acc[2][8][4];
        #pragma unroll
        for (int mb = 0; mb < 2; mb++)
            #pragma unroll
            for (int nb = 0; nb < 8; nb++)
                #pragma unroll
                for (int j = 0; j < 4; j++) acc[mb][nb][j] = 0.f;

        for (int w = 0; w < 8; w++) {
            if (have_next) {
                int g = (i + 1) * 8 + w;
                if (g + 1 >= gw_total) { CPA_WAIT0(); } else { CPA_WAITG1(); }
                convert_wave(smem, dstoff, g, donorm, tid);
                if (g + 2 < gw_total) prefetch_wave(X, t0, G, g + 2, sbase, tid);
                if (w == 0 && tid < 128) {
                    sAS[(p ^ 1) * 128 + tid] = 0.f;
                    sAD[(p ^ 1) * 128 + tid] = 0.f;
                }
            }
            int kofs = w * 16;
            uint32_t ah[2][4], al[2][4];
            ldm_x4(ah[0], aAddr + kofs * 2);
            ldm_x4(ah[1], aAddr + kofs * 2 + 16 * ASTRIDE * 2);
            ldm_x4(al[0], aAddr + (kofs + 128) * 2);
            ldm_x4(al[1], aAddr + (kofs + 128) * 2 + 16 * ASTRIDE * 2);
            #pragma unroll
            for (int nbp = 0; nbp < 4; nbp++) {
                uint32_t bh[4], bl[4];
                ldm_x4(bh, bAddr + kofs * 2 + nbp * 16 * ASTRIDE * 2);
                ldm_x4(bl, bAddr + (kofs + 128) * 2 + nbp * 16 * ASTRIDE * 2);
                #pragma unroll
                for (int mb = 0; mb < 2; mb++) {
                    mma16816(acc[mb][2 * nbp],     ah[mb], &bh[0]);
                    mma16816(acc[mb][2 * nbp + 1], ah[mb], &bh[2]);
                    mma16816(acc[mb][2 * nbp],     al[mb], &bh[0]);
                    mma16816(acc[mb][2 * nbp + 1], al[mb], &bh[2]);
                    mma16816(acc[mb][2 * nbp],     ah[mb], &bl[0]);
                    mma16816(acc[mb][2 * nbp + 1], ah[mb], &bl[2]);
                }
            }
        }
        __syncthreads();

        #pragma unroll
        for (int mb = 0; mb < 2; mb++) {
            int rlo = m0 + mb * 16 + qrow;
            int rhi = rlo + 8;
            float as_lo = 0.f, ad_lo = 0.f, as_hi = 0.f, ad_hi = 0.f;
            #pragma unroll
            for (int nb = 0; nb < 8; nb++) {
                int col = n0 + nb * 8 + qcol;
                float c0 = acc[mb][nb][0], c1 = acc[mb][nb][1];
                float c2 = acc[mb][nb][2], c3 = acc[mb][nb][3];
                float s0 = sAVS[col], s1 = sAVS[col + 1];
                float d0 = sAVD[col], d1 = sAVD[col + 1];
                as_lo += c0 * s0 + c1 * s1;  ad_lo += c0 * d0 + c1 * d1;
                as_hi += c2 * s0 + c3 * s1;  ad_hi += c2 * d0 + c3 * d1;
                if (rlo < nrows) {
                    float2* pp = (float2*)(Y + (long long)(row0 + rlo) * HH + col);
                    *pp = make_float2(c0, c1);
                }
                if (rhi < nrows) {
                    float2* pp = (float2*)(Y + (long long)(row0 + rhi) * HH + col);
                    *pp = make_float2(c2, c3);
                }
            }
            #pragma unroll
            for (int o = 1; o < 4; o <<= 1) {
                as_lo += __shfl_xor_sync(0xFFFFFFFFu, as_lo, o);
                ad_lo += __shfl_xor_sync(0xFFFFFFFFu, ad_lo, o);
                as_hi += __shfl_xor_sync(0xFFFFFFFFu, as_hi, o);
                ad_hi += __shfl_xor_sync(0xFFFFFFFFu, ad_hi, o);
            }
            if ((lane & 3) == 0) {
                atomicAdd(&sASp[rlo], as_lo); atomicAdd(&sADp[rlo], ad_lo);
                atomicAdd(&sASp[rhi], as_hi); atomicAdd(&sADp[rhi], ad_hi);
            }
        }
        __syncthreads();
        if (tid < nrows) {
            int r = row0 + tid;
            g_as[r] = sASp[tid]; g_ad[r] = sADp[tid];
        }
        if (!have_next) break;
        p ^= 1;
    }
}

// ---------------- GAT aggregation: batched phase-1, fused stats/pool ---------
__global__ void __launch_bounds__(256)
k_gat_agg(const float* __restrict__ hW, float* __restrict__ hout,
          const float* __restrict__ bias, int mode, int slot) {
    __shared__ float s_sum[HH], s_sq[HH];
    __shared__ int2 s_sa[8][NPW][32];
    int tid = threadIdx.x;
    int wid = tid >> 5, lane = tid & 31;
    if (mode == 1 && tid < HH) { s_sum[tid] = 0.f; s_sq[tid] = 0.f; }
    __syncthreads();

    float4 bb = ((const float4*)bias)[lane];
    int nbase = (blockIdx.x * 8 + wid) * NPW;

    int degs[NPW], rss[NPW], fd[NPW];
    float adv[NPW];
    #pragma unroll
    for (int n = 0; n < NPW; n++) {
        int node = nbase + n;
        int val = node < NN;
        rss[n] = val ? g_rowstart[node] : 0;
        int re = val ? g_rowstart[node + 1] : 0;
        degs[n] = re - rss[n];
        adv[n] = val ? g_ad[node] : 0.f;
        fd[n] = (degs[n] <= 32) ? degs[n] : 0;
    }
    int msrc[NPW];
    float exv[NPW];
    #pragma unroll
    for (int n = 0; n < NPW; n++)
        msrc[n] = (lane < fd[n]) ? g_ssrc[rss[n] + lane] : 0;
    #pragma unroll
    for (int n = 0; n < NPW; n++)
        exv[n] = (lane < fd[n]) ? __expf(lrelu(g_as[msrc[n]] + adv[n], 0.2f)) : 0.f;
    float sv[NPW];
    #pragma unroll
    for (int n = 0; n < NPW; n++) sv[n] = exv[n];
    #pragma unroll
    for (int o = 16; o; o >>= 1) {
        #pragma unroll
        for (int n = 0; n < NPW; n++)
            sv[n] += __shfl_xor_sync(0xFFFFFFFFu, sv[n], o);
    }
    #pragma unroll
    for (int n = 0; n < NPW; n++)
        s_sa[wid][n][lane] = make_int2(msrc[n],
                                       __float_as_int(exv[n] / (sv[n] + 1e-16f)));
    __syncwarp();

    float4 acc[NPW];
    #pragma unroll
    for (int n = 0; n < NPW; n++) acc[n] = bb;
    int dmax = 0;
    #pragma unroll
    for (int n = 0; n < NPW; n++) dmax = max(dmax, fd[n]);
    for (int j = 0; j < dmax; j++) {
        #pragma unroll
        for (int n = 0; n < NPW; n++) {
            if (j < fd[n]) {
                int2 sa = s_sa[wid][n][j];
                float al = __int_as_float(sa.y);
                float4 v = ((const float4*)(hW + (long long)sa.x * HH))[lane];
                acc[n].x += al * v.x; acc[n].y += al * v.y;
                acc[n].z += al * v.z; acc[n].w += al * v.w;
            }
        }
    }
    __syncwarp();
    #pragma unroll
    for (int n = 0; n < NPW; n++) {
        if (degs[n] > 32) {
            int rs = rss[n], re = rss[n] + degs[n];
            float m = -1e30f, s = 0.f;
            for (int i = rs + lane; i < re; i += 32) {
                int src = g_ssrc[i];
                float x = lrelu(g_as[src] + adv[n], 0.2f);
                if (x > m) { s = s * __expf(m - x) + 1.f; m = x; }
                else       { s += __expf(x - m); }
            }
            #pragma unroll
            for (int o = 16; o; o >>= 1) {
                float om = __shfl_xor_sync(0xFFFFFFFFu, m, o);
                float os = __shfl_xor_sync(0xFFFFFFFFu, s, o);
                float nm = fmaxf(m, om);
                s = s * __expf(m - nm) + os * __expf(om - nm);
                m = nm;
            }
            float inv = 1.f / (s + 1e-16f);
            for (int i = rs; i < re; ++i) {
                int src = g_ssrc[i];
                float alpha = __expf(lrelu(g_as[src] + adv[n], 0.2f) - m) * inv;
                float4 v = ((const float4*)(hW + (long long)src * HH))[lane];
                acc[n].x += alpha * v.x; acc[n].y += alpha * v.y;
                acc[n].z += alpha * v.z; acc[n].w += alpha * v.w;
            }
        }
    }

    float4 cs = make_float4(0.f, 0.f, 0.f, 0.f);
    float4 cq = make_float4(0.f, 0.f, 0.f, 0.f);
    float4 pacc = make_float4(0.f, 0.f, 0.f, 0.f);
    int curb = -1;
    #pragma unroll
    for (int n = 0; n < NPW; n++) {
        int node = nbase + n;
        if (node >= NN) break;
        float4 a = acc[n];
        if (mode == 2) {
            int b = g_batch[node];
            if (b != curb) {
                if (curb >= 0) red4(&g_pool[curb * HH + (lane << 2)], pacc);
                curb = b;
                pacc = make_float4(0.f, 0.f, 0.f, 0.f);
            }
            pacc.x += a.x; pacc.y += a.y; pacc.z += a.z; pacc.w += a.w;
        } else {
            ((float4*)(hout + (long long)node * HH))[lane] = a;
            if (mode == 1) {
                cs.x += a.x; cs.y += a.y; cs.z += a.z; cs.w += a.w;
                cq.x += a.x * a.x; cq.y += a.y * a.y;
                cq.z += a.z * a.z; cq.w += a.w * a.w;
            }
        }
    }

    if (mode == 2) {
        if (curb >= 0) red4(&g_pool[curb * HH + (lane << 2)], pacc);
    } else if (mode == 1) {
        int c0 = lane << 2;
        atomicAdd(&s_sum[c0],     cs.x); atomicAdd(&s_sum[c0 + 1], cs.y);
        atomicAdd(&s_sum[c0 + 2], cs.z); atomicAdd(&s_sum[c0 + 3], cs.w);
        atomicAdd(&s_sq[c0],      cq.x); atomicAdd(&s_sq[c0 + 1],  cq.y);
        atomicAdd(&s_sq[c0 + 2],  cq.z); atomicAdd(&s_sq[c0 + 3],  cq.w);
        __syncthreads();
        if (tid < HH) {
            atomicAdd(&g_colsum[slot][tid], s_sum[tid]);
            atomicAdd(&g_colsq[slot][tid], s_sq[tid]);
        }
    }
}

// ---------------- fused MLP ---------------------------------------------------
__global__ void k_mlp(const float* __restrict__ W1, const float* __restrict__ b1,
                      const float* __restrict__ W2, const float* __restrict__ b2,
                      float* __restrict__ out) {
    __shared__ float sp[HH], sz[HH];
    int g = blockIdx.x, c = threadIdx.x;
    sp[c] = g_pool[g * HH + c];
    __syncthreads();
    float a1 = b1[c];
    #pragma unroll 4
    for (int k = 0; k < HH; k++) a1 += sp[k] * W1[k * HH + c];
    sz[c] = lrelu(a1, 0.01f);
    __syncthreads();
    if (c < AA) {
        float a2 = b2[c];
        #pragma unroll 4
        for (int k = 0; k < HH; k++) a2 += sz[k] * W2[k * AA + c];
        out[g * AA + c] = a2;
    }
}

// ---------------- launcher ---------------------------------------------------
static cudaStream_t get_side_stream() {
    static cudaStream_t s = [] {
        cudaStream_t t;
        cudaStreamCreateWithFlags(&t, cudaStreamNonBlocking);
        return t;
    }();
    return s;
}
static cudaEvent_t get_event(int which) {
    static cudaEvent_t e[2] = { [] { cudaEvent_t t;
                                     cudaEventCreateWithFlags(&t, cudaEventDisableTiming);
                                     return t; }(),
                                [] { cudaEvent_t t;
                                     cudaEventCreateWithFlags(&t, cudaEventDisableTiming);
                                     return t; }() };
    return e[which];
}

extern "C" void kernel_launch(void* const* d_in, const int* in_sizes, int n_in,
                              void* d_out, int out_size) {
    const float* x        = (const float*)d_in[0];
    const void*  e_raw    = d_in[1];
    const void*  b_raw    = d_in[2];
    const float* Ws       = (const float*)d_in[3];
    const float* att_src  = (const float*)d_in[4];
    const float* att_dst  = (const float*)d_in[5];
    const float* conv_bias= (const float*)d_in[6];
    const float* gn_w     = (const float*)d_in[7];
    const float* gn_b     = (const float*)d_in[8];
    const float* gn_ms    = (const float*)d_in[9];
    const float* W1       = (const float*)d_in[10];
    const float* b1       = (const float*)d_in[11];
    const float* W2       = (const float*)d_in[12];
    const float* b2       = (const float*)d_in[13];

    float* bufA; float* bufB;
    cudaGetSymbolAddress((void**)&bufA, g_bufA);
    cudaGetSymbolAddress((void**)&bufB, g_bufB);

    cudaFuncSetAttribute(k_gemm_mma, cudaFuncAttributeMaxDynamicSharedMemorySize, GEMM_SMEM);

    cudaStream_t s2 = get_side_stream();
    cudaEvent_t evF = get_event(0), evJ = get_event(1);

    const int eg = (EE + 255) / 256;
    const int ng = (NN + 255) / 256;
    const int NB = (NN + 1023) / 1024;
    const int agg_grid = (NN + 8 * NPW - 1) / (8 * NPW);

    // ---- fork: CSR build on side stream; prepW + GEMM L0 on main stream ----
    cudaEventRecord(evF, 0);
    cudaStreamWaitEvent(s2, evF, 0);
    k_cvt<<<eg, 256, 0, s2>>>(e_raw, b_raw);
    k_scan1<<<NB, 256, 0, s2>>>();
    k_scan23<<<ng, 256, 0, s2>>>();
    k_fill<<<eg, 256, 0, s2>>>();
    cudaEventRecord(evJ, s2);

    k_prepW<<<(LL * HH * HH + 255) / 256, 256>>>(Ws);
    k_gemm_mma<<<148, 256, GEMM_SMEM>>>(x, 0, bufA, att_src, att_dst, 0, 0,
                                        gn_w, gn_b, gn_ms);
    cudaStreamWaitEvent(0, evJ, 0);

    for (int l = 0; l < LL; l++) {
        if (l > 0) {
            k_gemm_mma<<<148, 256, GEMM_SMEM>>>(bufB, l, bufA,
                                                att_src + l * HH, att_dst + l * HH,
                                                1, l - 1,
                                                gn_w + (l - 1) * HH, gn_b + (l - 1) * HH,
                                                gn_ms + (l - 1) * HH);
        }
        int mode = (l < LL - 1) ? 1 : 2;
        k_gat_agg<<<agg_grid, 256>>>(bufA, bufB, conv_bias + l * HH, mode, l);
    }

    k_mlp<<<GG, 128>>>(W1, b1, W2, b2, (float*)d_out);
}

// round 16
// speedup vs baseline: 1.9935x; 1.0168x over previous
#include <cuda_runtime.h>
#include <cuda_bf16.h>
#include <cstdint>

#define NN 100000
#define EE 600000
#define HH 128
#define AA 64
#define GG 64
#define LL 3
#define EPSN 1e-5f
#define NTILES 782
#define ASTRIDE 264
#define NPW 4

// ---------------- scratch (device globals) ----------------------------------
__device__ float g_bufA[NN * HH];
__device__ float g_bufB[NN * HH];
__device__ float g_as[NN], g_ad[NN];
__device__ int g_src[EE], g_dst[EE];
__device__ int g_batch[NN];
__device__ int g_deg[NN];
__device__ int g_rowstart[NN + 1];
__device__ int g_cursor[NN];
__device__ int g_ssrc[EE];
__device__ int g_bsum[128];
__device__ float g_colsum[2][HH], g_colsq[2][HH];
__device__ float g_pool[GG * HH];

__device__ __forceinline__ float lrelu(float x, float a) { return x > 0.f ? x : a * x; }

__device__ __forceinline__ uint32_t smem_u32(const void* p) {
    uint32_t a;
    asm("{ .reg .u64 t; cvta.to.shared.u64 t, %1; cvt.u32.u64 %0, t; }" : "=r"(a) : "l"(p));
    return a;
}
__device__ __forceinline__ void ldm_x4(uint32_t* r, uint32_t addr) {
    asm volatile("ldmatrix.sync.aligned.m8n8.x4.shared.b16 {%0,%1,%2,%3}, [%4];"
                 : "=r"(r[0]), "=r"(r[1]), "=r"(r[2]), "=r"(r[3]) : "r"(addr));
}
__device__ __forceinline__ void mma16816(float* c, const uint32_t* a, const uint32_t* b) {
    asm volatile("mma.sync.aligned.m16n8k16.row.col.f32.bf16.bf16.f32 "
                 "{%0,%1,%2,%3}, {%4,%5,%6,%7}, {%8,%9}, {%0,%1,%2,%3};"
                 : "+f"(c[0]), "+f"(c[1]), "+f"(c[2]), "+f"(c[3])
                 : "r"(a[0]), "r"(a[1]), "r"(a[2]), "r"(a[3]), "r"(b[0]), "r"(b[1]));
}
__device__ __forceinline__ void cpa16(uint32_t dst, const void* src, int sz) {
    asm volatile("cp.async.cg.shared.global [%0], [%1], 16, %2;"
                 :: "r"(dst), "l"(src), "r"(sz) : "memory");
}
#define CPA_COMMIT() asm volatile("cp.async.commit_group;" ::: "memory")
#define CPA_WAIT0()  asm volatile("cp.async.wait_group 0;" ::: "memory")
#define CPA_WAITG1() asm volatile("cp.async.wait_group 1;" ::: "memory")
__device__ __forceinline__ void red4(float* p, float4 v) {
    asm volatile("red.global.add.v4.f32 [%0], {%1,%2,%3,%4};"
                 :: "l"(p), "f"(v.x), "f"(v.y), "f"(v.z), "f"(v.w) : "memory");
}

// ---------------- cvt + inline dtype detection + histogram -------------------
__global__ void k_cvt(const void* eraw, const void* braw) {
    __shared__ int s_e32, s_b32;
    int tid = threadIdx.x;
    if (tid == 0) { s_e32 = 0; s_b32 = 0; }
    __syncthreads();
    if (tid < 64) {
        long long v = ((const long long*)eraw)[(long long)tid * (EE / 64)];
        if (v < 0 || v >= NN) atomicOr(&s_e32, 1);
    } else if (tid < 128) {
        long long bv = ((const long long*)braw)[(long long)(tid - 64) * ((NN / 2) / 64)];
        if (bv < 0 || bv >= GG) atomicOr(&s_b32, 1);
    }
    __syncthreads();
    int e32 = s_e32, b32 = s_b32;
    int i = blockIdx.x * blockDim.x + tid;
    if (i < EE) {
        int s, d;
        if (e32) {
            const int* p = (const int*)eraw;
            s = p[i]; d = p[EE + i];
        } else {
            const long long* p = (const long long*)eraw;
            s = (int)p[i]; d = (int)p[EE + i];
        }
        g_src[i] = s; g_dst[i] = d;
        atomicAdd(&g_deg[d], 1);
    }
    if (i < NN) {
        if (b32) g_batch[i] = ((const int*)braw)[i];
        else     g_batch[i] = (int)((const long long*)braw)[i];
    }
    if (i < GG * HH) g_pool[i] = 0.f;
    if (i < HH) {
        g_colsum[0][i] = 0.f; g_colsum[1][i] = 0.f;
        g_colsq[0][i] = 0.f;  g_colsq[1][i] = 0.f;
    }
}

// ---------------- CSR build -------------------------------------------------
__global__ void k_scan1() {
    __shared__ int s_w[8];
    int b = blockIdx.x, t = threadIdx.x;
    int base = b * 1024 + t * 4;
    int d[4];
    #pragma unroll
    for (int i = 0; i < 4; i++) d[i] = (base + i < NN) ? g_deg[base + i] : 0;
    int local = d[0] + d[1] + d[2] + d[3];
    int lane = t & 31, w = t >> 5;
    int v = local;
    #pragma unroll
    for (int o = 1; o < 32; o <<= 1) {
        int u = __shfl_up_sync(0xFFFFFFFFu, v, o);
        if (lane >= o) v += u;
    }
    if (lane == 31) s_w[w] = v;
    __syncthreads();
    if (t < 8) {
        int x = s_w[t];
        #pragma unroll
        for (int o = 1; o < 8; o <<= 1) {
            int u = __shfl_up_sync(0xFFu, x, o);
            if (t >= o) x += u;
        }
        s_w[t] = x;
    }
    __syncthreads();
    int warpoff = (w > 0) ? s_w[w - 1] : 0;
    int excl = warpoff + v - local;
    #pragma unroll
    for (int i = 0; i < 4; i++) {
        if (base + i < NN) g_rowstart[base + i] = excl;
        excl += d[i];
    }
    if (t == 0) g_bsum[b] = s_w[7];
}

__global__ void k_scan23() {
    __shared__ int sb[128];
    int t = threadIdx.x;
    int NB = (NN + 1023) / 1024;
    if (t < 128) sb[t] = (t < NB) ? g_bsum[t] : 0;
    __syncthreads();
    for (int o = 1; o < 128; o <<= 1) {
        int u = (t < 128 && t >= o) ? sb[t - o] : 0;
        __syncthreads();
        if (t < 128) sb[t] += u;
        __syncthreads();
    }
    int i = blockIdx.x * blockDim.x + t;
    if (i < NN) {
        int blk = i >> 10;
        int off = (blk > 0) ? sb[blk - 1] : 0;
        int v = g_rowstart[i] + off;
        g_rowstart[i] = v;
        g_cursor[i] = v;
        g_deg[i] = 0;
    }
    if (i == 0) g_rowstart[NN] = EE;
}

__global__ void k_fill() {
    int e = blockIdx.x * blockDim.x + threadIdx.x;
    if (e >= EE) return;
    int d = g_dst[e];
    int slot = atomicAdd(&g_cursor[d], 1);
    g_ssrc[slot] = g_src[e];
}

// ---------------- HMMA GEMM: persistent, wave-pipelined, PDL -----------------
#define SA_BYTES  (HH * ASTRIDE * 2)
#define SB_OFF    (2 * SA_BYTES)
#define STAGE_OFF (3 * SA_BYTES)
#define VEC_OFF   (STAGE_OFF + 3 * 8192)
#define SAS_OFF   (VEC_OFF)
#define SAD_OFF   (VEC_OFF + 1024)
#define SAVS_OFF  (VEC_OFF + 2048)
#define SAVD_OFF  (VEC_OFF + 2560)
#define SSH_OFF   (VEC_OFF + 3072)
#define SSC_OFF   (VEC_OFF + 3584)
#define SGB_OFF   (VEC_OFF + 4096)
#define GEMM_SMEM (VEC_OFF + 4608)

__device__ __forceinline__ void prefetch_wave(const float* __restrict__ X, int t0,
                                              int G, int g, uint32_t sbase, int tid) {
    int row0 = (t0 + (g >> 3) * G) << 7;
    int wv = g & 7;
    int nr = NN - row0; if (nr > 128) nr = 128;
    uint32_t stg = sbase + STAGE_OFF + (g % 3) * 8192;
    #pragma unroll
    for (int q = 0; q < 2; q++) {
        int cl = q * 256 + tid;
        int r = wv * 16 + (cl >> 5);
        int k4 = cl & 31;
        int rr = (r < nr) ? r : 0;
        cpa16(stg + cl * 16, ((const float4*)(X + (long long)(row0 + rr) * HH)) + k4,
              (r < nr) ? 16 : 0);
    }
    CPA_COMMIT();
}

__device__ __forceinline__ void convert_wave(char* smem, int dstoff, int g,
                                             int donorm, int tid) {
    const float4* stg = (const float4*)(smem + STAGE_OFF + (g % 3) * 8192);
    int wv = g & 7;
    #pragma unroll
    for (int q = 0; q < 2; q++) {
        int cl = q * 256 + tid;
        int r = wv * 16 + (cl >> 5);
        int k4 = cl & 31;
        float4 v = stg[cl];
        if (donorm) {
            float4 sh = ((const float4*)(smem + SSH_OFF))[k4];
            float4 sc = ((const float4*)(smem + SSC_OFF))[k4];
            float4 bb = ((const float4*)(smem + SGB_OFF))[k4];
            v.x = lrelu((v.x - sh.x) * sc.x + bb.x, 0.01f);
            v.y = lrelu((v.y - sh.y) * sc.y + bb.y, 0.01f);
            v.z = lrelu((v.z - sh.z) * sc.z + bb.z, 0.01f);
            v.w = lrelu((v.w - sh.w) * sc.w + bb.w, 0.01f);
        }
        __nv_bfloat16 h0 = __float2bfloat16_rn(v.x), h1 = __float2bfloat16_rn(v.y);
        __nv_bfloat16 h2 = __float2bfloat16_rn(v.z), h3 = __float2bfloat16_rn(v.w);
        __nv_bfloat162 hp0; hp0.x = h0; hp0.y = h1;
        __nv_bfloat162 hp1; hp1.x = h2; hp1.y = h3;
        __nv_bfloat162 lp0 = __floats2bfloat162_rn(v.x - __bfloat162float(h0),
                                                   v.y - __bfloat162float(h1));
        __nv_bfloat162 lp1 = __floats2bfloat162_rn(v.z - __bfloat162float(h2),
                                                   v.w - __bfloat162float(h3));
        int k0 = k4 << 2;
        uint2 hv = make_uint2(*(unsigned*)&hp0, *(unsigned*)&hp1);
        uint2 lv = make_uint2(*(unsigned*)&lp0, *(unsigned*)&lp1);
        *(uint2*)(smem + dstoff + (r * ASTRIDE + k0) * 2) = hv;
        *(uint2*)(smem + dstoff + (r * ASTRIDE + 128 + k0) * 2) = lv;
    }
}

__global__ void __launch_bounds__(256, 1)
k_gemm_mma(const float* __restrict__ X, const float* __restrict__ Wl,
           float* __restrict__ Y,
           const float* __restrict__ avs, const float* __restrict__ avd,
           int donorm, int slot,
           const float* __restrict__ gnw, const float* __restrict__ gnb,
           const float* __restrict__ gnms) {
    extern __shared__ char smem[];
    uint32_t sbase = smem_u32(smem);
    int tid = threadIdx.x;
    int wid = tid >> 5, lane = tid & 31;
    int G = gridDim.x;
    int t0 = blockIdx.x;
    int ntb = (NTILES - t0 + G - 1) / G;
    int gw_total = ntb * 8;

    float* sAS = (float*)(smem + SAS_OFF);
    float* sAD = (float*)(smem + SAD_OFF);
    float* sAVS = (float*)(smem + SAVS_OFF);
    float* sAVD = (float*)(smem + SAVD_OFF);

    // ---- producer-independent preamble ----
    if (tid < 128) {
        sAVS[tid] = avs[tid];
        sAVD[tid] = avd[tid];
        sAS[tid] = 0.f; sAD[tid] = 0.f;
    }
    {
        // W split directly from raw Ws (L2-hot)
        __nv_bfloat16* sB = (__nv_bfloat16*)(smem + SB_OFF);
        for (int i = tid; i < HH * HH; i += 256) {
            int k = i >> 7, n = i & 127;
            float w = Wl[i];
            __nv_bfloat16 hi = __float2bfloat16_rn(w);
            __nv_bfloat16 lo = __float2bfloat16_rn(w - __bfloat162float(hi));
            sB[n * ASTRIDE + k] = hi;
            sB[n * ASTRIDE + 128 + k] = lo;
        }
    }

    // ---- wait for producer (previous agg) results ----
    cudaGridDependencySynchronize();

    if (donorm && tid < 128) {
        float invN = 1.0f / (float)NN;
        float mean = __ldcg(&g_colsum[slot][tid]) * invN;
        float ex2 = __ldcg(&g_colsq[slot][tid]) * invN;
        float s = gnms[tid];
        float var = ex2 - 2.f * s * mean * mean + s * s * mean * mean;
        ((float*)(smem + SSH_OFF))[tid] = mean * s;
        ((float*)(smem + SSC_OFF))[tid] = gnw[tid] * rsqrtf(var + EPSN);
        ((float*)(smem + SGB_OFF))[tid] = gnb[tid];
    }
    __syncthreads();

    prefetch_wave(X, t0, G, 0, sbase, tid);
    prefetch_wave(X, t0, G, 1, sbase, tid);
    for (int w = 0; w < 8; w++) {
        if (w + 1 >= gw_total) { CPA_WAIT0(); } else { CPA_WAITG1(); }
        convert_wave(smem, 0, w, donorm, tid);
        if (w + 2 < gw_total) prefetch_wave(X, t0, G, w + 2, sbase, tid);
    }
    __syncthreads();

    int m0 = (wid >> 1) << 5;
    int n0 = (wid & 1) << 6;
    int arow = m0 + (lane & 7) + ((lane >> 3) & 1) * 8;
    uint32_t aBase = sbase + (arow * ASTRIDE + ((lane >> 4) & 1) * 8) * 2;
    int brow = n0 + (lane & 7) + ((lane >> 4) & 1) * 8;
    uint32_t bAddr = sbase + SB_OFF + (brow * ASTRIDE + ((lane >> 3) & 1) * 8) * 2;
    int qrow = lane >> 2;
    int qcol = (lane & 3) << 1;

    int p = 0;
    for (int i = 0; ; i++) {
        int t = t0 + i * G;
        int row0 = t << 7;
        int nrows = NN - row0; if (nrows > 128) nrows = 128;
        int have_next = (i + 1 < ntb);
        uint32_t aAddr = aBase + p * SA_BYTES;
        int dstoff = (p ^ 1) * SA_BYTES;
        float* sASp = sAS + p * 128;
        float* sADp = sAD + p * 128;

        float acc[2][8][4];
        #pragma unroll
        for (int mb = 0; mb < 2; mb++)
            #pragma unroll
            for (int nb = 0; nb < 8; nb++)
                #pragma unroll
                for (int j = 0; j < 4; j++) acc[mb][nb][j] = 0.f;

        for (int w = 0; w < 8; w++) {
            if (have_next) {
                int g = (i + 1) * 8 + w;
                if (g + 1 >= gw_total) { CPA_WAIT0(); } else { CPA_WAITG1(); }
                convert_wave(smem, dstoff, g, donorm, tid);
                if (g + 2 < gw_total) prefetch_wave(X, t0, G, g + 2, sbase, tid);
                if (w == 0 && tid < 128) {
                    sAS[(p ^ 1) * 128 + tid] = 0.f;
                    sAD[(p ^ 1) * 128 + tid] = 0.f;
                }
            }
            int kofs = w * 16;
            uint32_t ah[2][4], al[2][4];
            ldm_x4(ah[0], aAddr + kofs * 2);
            ldm_x4(ah[1], aAddr + kofs * 2 + 16 * ASTRIDE * 2);
            ldm_x4(al[0], aAddr + (kofs + 128) * 2);
            ldm_x4(al[1], aAddr + (kofs + 128) * 2 + 16 * ASTRIDE * 2);
            #pragma unroll
            for (int nbp = 0; nbp < 4; nbp++) {
                uint32_t bh[4], bl[4];
                ldm_x4(bh, bAddr + kofs * 2 + nbp * 16 * ASTRIDE * 2);
                ldm_x4(bl, bAddr + (kofs + 128) * 2 + nbp * 16 * ASTRIDE * 2);
                #pragma unroll
                for (int mb = 0; mb < 2; mb++) {
                    mma16816(acc[mb][2 * nbp],     ah[mb], &bh[0]);
                    mma16816(acc[mb][2 * nbp + 1], ah[mb], &bh[2]);
                    mma16816(acc[mb][2 * nbp],     al[mb], &bh[0]);
                    mma16816(acc[mb][2 * nbp + 1], al[mb], &bh[2]);
                    mma16816(acc[mb][2 * nbp],     ah[mb], &bl[0]);
                    mma16816(acc[mb][2 * nbp + 1], ah[mb], &bl[2]);
                }
            }
        }
        __syncthreads();

        #pragma unroll
        for (int mb = 0; mb < 2; mb++) {
            int rlo = m0 + mb * 16 + qrow;
            int rhi = rlo + 8;
            float as_lo = 0.f, ad_lo = 0.f, as_hi = 0.f, ad_hi = 0.f;
            #pragma unroll
            for (int nb = 0; nb < 8; nb++) {
                int col = n0 + nb * 8 + qcol;
                float c0 = acc[mb][nb][0], c1 = acc[mb][nb][1];
                float c2 = acc[mb][nb][2], c3 = acc[mb][nb][3];
                float s0 = sAVS[col], s1 = sAVS[col + 1];
                float d0 = sAVD[col], d1 = sAVD[col + 1];
                as_lo += c0 * s0 + c1 * s1;  ad_lo += c0 * d0 + c1 * d1;
                as_hi += c2 * s0 + c3 * s1;  ad_hi += c2 * d0 + c3 * d1;
                if (rlo < nrows) {
                    float2* pp = (float2*)(Y + (long long)(row0 + rlo) * HH + col);
                    *pp = make_float2(c0, c1);
                }
                if (rhi < nrows) {
                    float2* pp = (float2*)(Y + (long long)(row0 + rhi) * HH + col);
                    *pp = make_float2(c2, c3);
                }
            }
            #pragma unroll
            for (int o = 1; o < 4; o <<= 1) {
                as_lo += __shfl_xor_sync(0xFFFFFFFFu, as_lo, o);
                ad_lo += __shfl_xor_sync(0xFFFFFFFFu, ad_lo, o);
                as_hi += __shfl_xor_sync(0xFFFFFFFFu, as_hi, o);
                ad_hi += __shfl_xor_sync(0xFFFFFFFFu, ad_hi, o);
            }
            if ((lane & 3) == 0) {
                atomicAdd(&sASp[rlo], as_lo); atomicAdd(&sADp[rlo], ad_lo);
                atomicAdd(&sASp[rhi], as_hi); atomicAdd(&sADp[rhi], ad_hi);
            }
        }
        __syncthreads();
        if (tid < nrows) {
            int r = row0 + tid;
            g_as[r] = sASp[tid]; g_ad[r] = sADp[tid];
        }
        if (!have_next) break;
        p ^= 1;
    }
}

// ---------------- GAT aggregation: PDL, batched phase-1, fused stats/pool ----
__global__ void __launch_bounds__(256)
k_gat_agg(const float* __restrict__ hW, float* __restrict__ hout,
          const float* __restrict__ bias, int mode, int slot) {
    __shared__ float s_sum[HH], s_sq[HH];
    __shared__ int2 s_sa[8][NPW][32];
    int tid = threadIdx.x;
    int wid = tid >> 5, lane = tid & 31;
    if (mode == 1 && tid < HH) { s_sum[tid] = 0.f; s_sq[tid] = 0.f; }
    __syncthreads();

    float4 bb = ((const float4*)bias)[lane];
    int nbase = (blockIdx.x * 8 + wid) * NPW;

    // ---- producer-independent: CSR index loads ----
    int degs[NPW], rss[NPW], fd[NPW];
    #pragma unroll
    for (int n = 0; n < NPW; n++) {
        int node = nbase + n;
        int val = node < NN;
        rss[n] = val ? g_rowstart[node] : 0;
        int re = val ? g_rowstart[node + 1] : 0;
        degs[n] = re - rss[n];
        fd[n] = (degs[n] <= 32) ? degs[n] : 0;
    }
    int msrc[NPW];
    #pragma unroll
    for (int n = 0; n < NPW; n++)
        msrc[n] = (lane < fd[n]) ? g_ssrc[rss[n] + lane] : 0;

    // ---- wait for producer GEMM ----
    cudaGridDependencySynchronize();

    float adv[NPW];
    #pragma unroll
    for (int n = 0; n < NPW; n++)
        adv[n] = (nbase + n < NN) ? g_ad[nbase + n] : 0.f;
    float exv[NPW];
    #pragma unroll
    for (int n = 0; n < NPW; n++)
        exv[n] = (lane < fd[n]) ? __expf(lrelu(g_as[msrc[n]] + adv[n], 0.2f)) : 0.f;
    float sv[NPW];
    #pragma unroll
    for (int n = 0; n < NPW; n++) sv[n] = exv[n];
    #pragma unroll
    for (int o = 16; o; o >>= 1) {
        #pragma unroll
        for (int n = 0; n < NPW; n++)
            sv[n] += __shfl_xor_sync(0xFFFFFFFFu, sv[n], o);
    }
    #pragma unroll
    for (int n = 0; n < NPW; n++)
        s_sa[wid][n][lane] = make_int2(msrc[n],
                                       __float_as_int(exv[n] / (sv[n] + 1e-16f)));
    __syncwarp();

    float4 acc[NPW];
    #pragma unroll
    for (int n = 0; n < NPW; n++) acc[n] = bb;
    int dmax = 0;
    #pragma unroll
    for (int n = 0; n < NPW; n++) dmax = max(dmax, fd[n]);
    for (int j = 0; j < dmax; j++) {
        #pragma unroll
        for (int n = 0; n < NPW; n++) {
            if (j < fd[n]) {
                int2 sa = s_sa[wid][n][j];
                float al = __int_as_float(sa.y);
                float4 v = ((const float4*)(hW + (long long)sa.x * HH))[lane];
                acc[n].x += al * v.x; acc[n].y += al * v.y;
                acc[n].z += al * v.z; acc[n].w += al * v.w;
            }
        }
    }
    __syncwarp();
    #pragma unroll
    for (int n = 0; n < NPW; n++) {
        if (degs[n] > 32) {
            int rs = rss[n], re = rss[n] + degs[n];
            float m = -1e30f, s = 0.f;
            for (int i = rs + lane; i < re; i += 32) {
                int src = g_ssrc[i];
                float x = lrelu(g_as[src] + adv[n], 0.2f);
                if (x > m) { s = s * __expf(m - x) + 1.f; m = x; }
                else       { s += __expf(x - m); }
            }
            #pragma unroll
            for (int o = 16; o; o >>= 1) {
                float om = __shfl_xor_sync(0xFFFFFFFFu, m, o);
                float os = __shfl_xor_sync(0xFFFFFFFFu, s, o);
                float nm = fmaxf(m, om);
                s = s * __expf(m - nm) + os * __expf(om - nm);
                m = nm;
            }
            float inv = 1.f / (s + 1e-16f);
            for (int i = rs; i < re; ++i) {
                int src = g_ssrc[i];
                float alpha = __expf(lrelu(g_as[src] + adv[n], 0.2f) - m) * inv;
                float4 v = ((const float4*)(hW + (long long)src * HH))[lane];
                acc[n].x += alpha * v.x; acc[n].y += alpha * v.y;
                acc[n].z += alpha * v.z; acc[n].w += alpha * v.w;
            }
        }
    }

    float4 cs = make_float4(0.f, 0.f, 0.f, 0.f);
    float4 cq = make_float4(0.f, 0.f, 0.f, 0.f);
    float4 pacc = make_float4(0.f, 0.f, 0.f, 0.f);
    int curb = -1;
    #pragma unroll
    for (int n = 0; n < NPW; n++) {
        int node = nbase + n;
        if (node >= NN) break;
        float4 a = acc[n];
        if (mode == 2) {
            int b = g_batch[node];
            if (b != curb) {
                if (curb >= 0) red4(&g_pool[curb * HH + (lane << 2)], pacc);
                curb = b;
                pacc = make_float4(0.f, 0.f, 0.f, 0.f);
            }
            pacc.x += a.x; pacc.y += a.y; pacc.z += a.z; pacc.w += a.w;
        } else {
            ((float4*)(hout + (long long)node * HH))[lane] = a;
            if (mode == 1) {
                cs.x += a.x; cs.y += a.y; cs.z += a.z; cs.w += a.w;
                cq.x += a.x * a.x; cq.y += a.y * a.y;
                cq.z += a.z * a.z; cq.w += a.w * a.w;
            }
        }
    }

    if (mode == 2) {
        if (curb >= 0) red4(&g_pool[curb * HH + (lane << 2)], pacc);
    } else if (mode == 1) {
        int c0 = lane << 2;
        atomicAdd(&s_sum[c0],     cs.x); atomicAdd(&s_sum[c0 + 1], cs.y);
        atomicAdd(&s_sum[c0 + 2], cs.z); atomicAdd(&s_sum[c0 + 3], cs.w);
        atomicAdd(&s_sq[c0],      cq.x); atomicAdd(&s_sq[c0 + 1],  cq.y);
        atomicAdd(&s_sq[c0 + 2],  cq.z); atomicAdd(&s_sq[c0 + 3],  cq.w);
        __syncthreads();
        if (tid < HH) {
            atomicAdd(&g_colsum[slot][tid], s_sum[tid]);
            atomicAdd(&g_colsq[slot][tid], s_sq[tid]);
        }
    }
}

// ---------------- fused MLP (PDL) ---------------------------------------------
__global__ void k_mlp(const float* __restrict__ W1, const float* __restrict__ b1,
                      const float* __restrict__ W2, const float* __restrict__ b2,
                      float* __restrict__ out) {
    __shared__ float sp[HH], sz[HH];
    int g = blockIdx.x, c = threadIdx.x;
    cudaGridDependencySynchronize();
    sp[c] = g_pool[g * HH + c];
    __syncthreads();
    float a1 = b1[c];
    #pragma unroll 4
    for (int k = 0; k < HH; k++) a1 += sp[k] * W1[k * HH + c];
    sz[c] = lrelu(a1, 0.01f);
    __syncthreads();
    if (c < AA) {
        float a2 = b2[c];
        #pragma unroll 4
        for (int k = 0; k < HH; k++) a2 += sz[k] * W2[k * AA + c];
        out[g * AA + c] = a2;
    }
}

// ---------------- launcher ---------------------------------------------------
static cudaStream_t get_side_stream() {
    static cudaStream_t s = [] {
        cudaStream_t t;
        cudaStreamCreateWithFlags(&t, cudaStreamNonBlocking);
        return t;
    }();
    return s;
}
static cudaEvent_t get_event(int which) {
    static cudaEvent_t e[2] = { [] { cudaEvent_t t;
                                     cudaEventCreateWithFlags(&t, cudaEventDisableTiming);
                                     return t; }(),
                                [] { cudaEvent_t t;
                                     cudaEventCreateWithFlags(&t, cudaEventDisableTiming);
                                     return t; }() };
    return e[which];
}

template <typename F, typename... Args>
static void launch_pdl(F f, dim3 grid, dim3 block, size_t smem, cudaStream_t st,
                       Args... args) {
    cudaLaunchConfig_t cfg = {};
    cfg.gridDim = grid;
    cfg.blockDim = block;
    cfg.dynamicSmemBytes = smem;
    cfg.stream = st;
    cudaLaunchAttribute attr[1];
    attr[0].id = cudaLaunchAttributeProgrammaticStreamSerialization;
    attr[0].val.programmaticStreamSerializationAllowed = 1;
    cfg.attrs = attr;
    cfg.numAttrs = 1;
    cudaLaunchKernelEx(&cfg, f, args...);
}

extern "C" void kernel_launch(void* const* d_in, const int* in_sizes, int n_in,
                              void* d_out, int out_size) {
    const float* x        = (const float*)d_in[0];
    const void*  e_raw    = d_in[1];
    const void*  b_raw    = d_in[2];
    const float* Ws       = (const float*)d_in[3];
    const float* att_src  = (const float*)d_in[4];
    const float* att_dst  = (const float*)d_in[5];
    const float* conv_bias= (const float*)d_in[6];
    const float* gn_w     = (const float*)d_in[7];
    const float* gn_b     = (const float*)d_in[8];
    const float* gn_ms    = (const float*)d_in[9];
    const float* W1       = (const float*)d_in[10];
    const float* b1       = (const float*)d_in[11];
    const float* W2       = (const float*)d_in[12];
    const float* b2       = (const float*)d_in[13];

    float* bufA; float* bufB;
    cudaGetSymbolAddress((void**)&bufA, g_bufA);
    cudaGetSymbolAddress((void**)&bufB, g_bufB);

    cudaFuncSetAttribute(k_gemm_mma, cudaFuncAttributeMaxDynamicSharedMemorySize, GEMM_SMEM);

    cudaStream_t s2 = get_side_stream();
    cudaEvent_t evF = get_event(0), evJ = get_event(1);

    const int eg = (EE + 255) / 256;
    const int ng = (NN + 255) / 256;
    const int NB = (NN + 1023) / 1024;
    const int agg_grid = (NN + 8 * NPW - 1) / (8 * NPW);

    // ---- fork: CSR build on side stream; GEMM L0 on main stream ----
    cudaEventRecord(evF, 0);
    cudaStreamWaitEvent(s2, evF, 0);
    k_cvt<<<eg, 256, 0, s2>>>(e_raw, b_raw);
    k_scan1<<<NB, 256, 0, s2>>>();
    k_scan23<<<ng, 256, 0, s2>>>();
    k_fill<<<eg, 256, 0, s2>>>();
    cudaEventRecord(evJ, s2);

    k_gemm_mma<<<148, 256, GEMM_SMEM>>>(x, Ws, bufA, att_src, att_dst, 0, 0,
                                        gn_w, gn_b, gn_ms);
    cudaStreamWaitEvent(0, evJ, 0);

    for (int l = 0; l < LL; l++) {
        if (l > 0) {
            launch_pdl(k_gemm_mma, dim3(148), dim3(256), (size_t)GEMM_SMEM,
                       (cudaStream_t)0,
                       (const float*)bufB, Ws + l * HH * HH, bufA,
                       att_src + l * HH, att_dst + l * HH,
                       1, l - 1,
                       gn_w + (l - 1) * HH, gn_b + (l - 1) * HH,
                       gn_ms + (l - 1) * HH);
        }
        int mode = (l < LL - 1) ? 1 : 2;
        launch_pdl(k_gat_agg, dim3(agg_grid), dim3(256), (size_t)0,
                   (cudaStream_t)0,
                   (const float*)bufA, bufB, conv_bias + l * HH, mode, l);
    }

    launch_pdl(k_mlp, dim3(GG), dim3(128), (size_t)0, (cudaStream_t)0,
               W1, b1, W2, b2, (float*)d_out);
}

// round 17
// speedup vs baseline: 2.0229x; 1.0148x over previous
#include <cuda_runtime.h>
#include <cuda_bf16.h>
#include <cstdint>

#define NN 100000
#define EE 600000
#define HH 128
#define AA 64
#define GG 64
#define LL 3
#define EPSN 1e-5f
#define NTILES 782
#define ASTRIDE 264
#define NPW 4

// ---------------- scratch (device globals) ----------------------------------
__device__ float g_bufA[NN * HH];
__device__ float g_bufB[NN * HH];
__device__ float g_as[NN], g_ad[NN];
__device__ int g_src[EE], g_dst[EE];
__device__ int g_batch[NN];
__device__ int g_deg[NN];
__device__ int g_rowstart[NN + 1];
__device__ int g_cursor[NN];
__device__ int g_ssrc[EE];
__device__ int g_bsum[128];
__device__ float g_colsum[2][HH], g_colsq[2][HH];
__device__ float g_pool[GG * HH];

__device__ __forceinline__ float lrelu(float x, float a) { return x > 0.f ? x : a * x; }

__device__ __forceinline__ uint32_t smem_u32(const void* p) {
    uint32_t a;
    asm("{ .reg .u64 t; cvta.to.shared.u64 t, %1; cvt.u32.u64 %0, t; }" : "=r"(a) : "l"(p));
    return a;
}
__device__ __forceinline__ void ldm_x4(uint32_t* r, uint32_t addr) {
    asm volatile("ldmatrix.sync.aligned.m8n8.x4.shared.b16 {%0,%1,%2,%3}, [%4];"
                 : "=r"(r[0]), "=r"(r[1]), "=r"(r[2]), "=r"(r[3]) : "r"(addr));
}
__device__ __forceinline__ void mma16816(float* c, const uint32_t* a, const uint32_t* b) {
    asm volatile("mma.sync.aligned.m16n8k16.row.col.f32.bf16.bf16.f32 "
                 "{%0,%1,%2,%3}, {%4,%5,%6,%7}, {%8,%9}, {%0,%1,%2,%3};"
                 : "+f"(c[0]), "+f"(c[1]), "+f"(c[2]), "+f"(c[3])
                 : "r"(a[0]), "r"(a[1]), "r"(a[2]), "r"(a[3]), "r"(b[0]), "r"(b[1]));
}
__device__ __forceinline__ void cpa16(uint32_t dst, const void* src, int sz) {
    asm volatile("cp.async.cg.shared.global [%0], [%1], 16, %2;"
                 :: "r"(dst), "l"(src), "r"(sz) : "memory");
}
#define CPA_COMMIT() asm volatile("cp.async.commit_group;" ::: "memory")
#define CPA_WAIT0()  asm volatile("cp.async.wait_group 0;" ::: "memory")
#define CPA_WAITG1() asm volatile("cp.async.wait_group 1;" ::: "memory")
__device__ __forceinline__ void red4(float* p, float4 v) {
    asm volatile("red.global.add.v4.f32 [%0], {%1,%2,%3,%4};"
                 :: "l"(p), "f"(v.x), "f"(v.y), "f"(v.z), "f"(v.w) : "memory");
}
// pack cvt.rn of (a -> low half, b -> high half)
__device__ __forceinline__ unsigned cvt_bf16x2(float hi_src, float lo_src) {
    unsigned r;
    asm("cvt.rn.bf16x2.f32 %0, %1, %2;" : "=r"(r) : "f"(hi_src), "f"(lo_src));
    return r;
}

// ---------------- cvt + inline dtype detection + histogram -------------------
__global__ void k_cvt(const void* eraw, const void* braw) {
    __shared__ int s_e32, s_b32;
    int tid = threadIdx.x;
    if (tid == 0) { s_e32 = 0; s_b32 = 0; }
    __syncthreads();
    if (tid < 64) {
        long long v = ((const long long*)eraw)[(long long)tid * (EE / 64)];
        if (v < 0 || v >= NN) atomicOr(&s_e32, 1);
    } else if (tid < 128) {
        long long bv = ((const long long*)braw)[(long long)(tid - 64) * ((NN / 2) / 64)];
        if (bv < 0 || bv >= GG) atomicOr(&s_b32, 1);
    }
    __syncthreads();
    int e32 = s_e32, b32 = s_b32;
    int i = blockIdx.x * blockDim.x + tid;
    if (i < EE) {
        int s, d;
        if (e32) {
            const int* p = (const int*)eraw;
            s = p[i]; d = p[EE + i];
        } else {
            const long long* p = (const long long*)eraw;
            s = (int)p[i]; d = (int)p[EE + i];
        }
        g_src[i] = s; g_dst[i] = d;
        atomicAdd(&g_deg[d], 1);
    }
    if (i < NN) {
        if (b32) g_batch[i] = ((const int*)braw)[i];
        else     g_batch[i] = (int)((const long long*)braw)[i];
    }
    if (i < GG * HH) g_pool[i] = 0.f;
    if (i < HH) {
        g_colsum[0][i] = 0.f; g_colsum[1][i] = 0.f;
        g_colsq[0][i] = 0.f;  g_colsq[1][i] = 0.f;
    }
}

// ---------------- CSR build -------------------------------------------------
__global__ void k_scan1() {
    __shared__ int s_w[8];
    int b = blockIdx.x, t = threadIdx.x;
    int base = b * 1024 + t * 4;
    int d[4];
    #pragma unroll
    for (int i = 0; i < 4; i++) d[i] = (base + i < NN) ? g_deg[base + i] : 0;
    int local = d[0] + d[1] + d[2] + d[3];
    int lane = t & 31, w = t >> 5;
    int v = local;
    #pragma unroll
    for (int o = 1; o < 32; o <<= 1) {
        int u = __shfl_up_sync(0xFFFFFFFFu, v, o);
        if (lane >= o) v += u;
    }
    if (lane == 31) s_w[w] = v;
    __syncthreads();
    if (t < 8) {
        int x = s_w[t];
        #pragma unroll
        for (int o = 1; o < 8; o <<= 1) {
            int u = __shfl_up_sync(0xFFu, x, o);
            if (t >= o) x += u;
        }
        s_w[t] = x;
    }
    __syncthreads();
    int warpoff = (w > 0) ? s_w[w - 1] : 0;
    int excl = warpoff + v - local;
    #pragma unroll
    for (int i = 0; i < 4; i++) {
        if (base + i < NN) g_rowstart[base + i] = excl;
        excl += d[i];
    }
    if (t == 0) g_bsum[b] = s_w[7];
}

__global__ void k_scan23() {
    __shared__ int sb[128];
    int t = threadIdx.x;
    int NB = (NN + 1023) / 1024;
    if (t < 128) sb[t] = (t < NB) ? g_bsum[t] : 0;
    __syncthreads();
    for (int o = 1; o < 128; o <<= 1) {
        int u = (t < 128 && t >= o) ? sb[t - o] : 0;
        __syncthreads();
        if (t < 128) sb[t] += u;
        __syncthreads();
    }
    int i = blockIdx.x * blockDim.x + t;
    if (i < NN) {
        int blk = i >> 10;
        int off = (blk > 0) ? sb[blk - 1] : 0;
        int v = g_rowstart[i] + off;
        g_rowstart[i] = v;
        g_cursor[i] = v;
        g_deg[i] = 0;
    }
    if (i == 0) g_rowstart[NN] = EE;
}

__global__ void k_fill() {
    int e = blockIdx.x * blockDim.x + threadIdx.x;
    if (e >= EE) return;
    int d = g_dst[e];
    int slot = atomicAdd(&g_cursor[d], 1);
    g_ssrc[slot] = g_src[e];
}

// ---------------- HMMA GEMM: persistent, wave-pipelined, PDL -----------------
#define SA_BYTES  (HH * ASTRIDE * 2)
#define SB_OFF    (2 * SA_BYTES)
#define STAGE_OFF (3 * SA_BYTES)
#define VEC_OFF   (STAGE_OFF + 3 * 8192)
#define SAS_OFF   (VEC_OFF)
#define SAD_OFF   (VEC_OFF + 1024)
#define SAVS_OFF  (VEC_OFF + 2048)
#define SAVD_OFF  (VEC_OFF + 2560)
#define SSC_OFF   (VEC_OFF + 3072)   // norm scale
#define SOF_OFF   (VEC_OFF + 3584)   // norm offset (b - shift*scale)
#define GEMM_SMEM (VEC_OFF + 4608)

__device__ __forceinline__ void prefetch_wave(const float* __restrict__ X, int t0,
                                              int G, int g, uint32_t sbase, int tid) {
    int row0 = (t0 + (g >> 3) * G) << 7;
    int wv = g & 7;
    int nr = NN - row0; if (nr > 128) nr = 128;
    uint32_t stg = sbase + STAGE_OFF + (g % 3) * 8192;
    #pragma unroll
    for (int q = 0; q < 2; q++) {
        int cl = q * 256 + tid;
        int r = wv * 16 + (cl >> 5);
        int k4 = cl & 31;
        int rr = (r < nr) ? r : 0;
        cpa16(stg + cl * 16, ((const float4*)(X + (long long)(row0 + rr) * HH)) + k4,
              (r < nr) ? 16 : 0);
    }
    CPA_COMMIT();
}

__device__ __forceinline__ void convert_wave(char* smem, int dstoff, int g,
                                             int donorm, int tid) {
    const float4* stg = (const float4*)(smem + STAGE_OFF + (g % 3) * 8192);
    int wv = g & 7;
    #pragma unroll
    for (int q = 0; q < 2; q++) {
        int cl = q * 256 + tid;
        int r = wv * 16 + (cl >> 5);
        int k4 = cl & 31;
        float4 v = stg[cl];
        if (donorm) {
            float4 sc = ((const float4*)(smem + SSC_OFF))[k4];
            float4 of = ((const float4*)(smem + SOF_OFF))[k4];
            v.x = fmaf(v.x, sc.x, of.x);
            v.y = fmaf(v.y, sc.y, of.y);
            v.z = fmaf(v.z, sc.z, of.z);
            v.w = fmaf(v.w, sc.w, of.w);
            v.x = fmaxf(v.x, 0.01f * v.x);
            v.y = fmaxf(v.y, 0.01f * v.y);
            v.z = fmaxf(v.z, 0.01f * v.z);
            v.w = fmaxf(v.w, 0.01f * v.w);
        }
        // truncation split: hi = top 16 bits (exact residual captured by lo)
        unsigned bx = __float_as_uint(v.x), by = __float_as_uint(v.y);
        unsigned bz = __float_as_uint(v.z), bw = __float_as_uint(v.w);
        unsigned hi01 = __byte_perm(bx, by, 0x7632);
        unsigned hi23 = __byte_perm(bz, bw, 0x7632);
        float lx = v.x - __uint_as_float(bx & 0xFFFF0000u);
        float ly = v.y - __uint_as_float(by & 0xFFFF0000u);
        float lz = v.z - __uint_as_float(bz & 0xFFFF0000u);
        float lw = v.w - __uint_as_float(bw & 0xFFFF0000u);
        unsigned lo01 = cvt_bf16x2(ly, lx);   // hi half <- ly, lo half <- lx
        unsigned lo23 = cvt_bf16x2(lw, lz);
        int k0 = k4 << 2;
        *(uint2*)(smem + dstoff + (r * ASTRIDE + k0) * 2) = make_uint2(hi01, hi23);
        *(uint2*)(smem + dstoff + (r * ASTRIDE + 128 + k0) * 2) = make_uint2(lo01, lo23);
    }
}

__global__ void __launch_bounds__(256, 1)
k_gemm_mma(const float* __restrict__ X, const float* __restrict__ Wl,
           float* __restrict__ Y,
           const float* __restrict__ avs, const float* __restrict__ avd,
           int donorm, int slot,
           const float* __restrict__ gnw, const float* __restrict__ gnb,
           const float* __restrict__ gnms) {
    extern __shared__ char smem[];
    uint32_t sbase = smem_u32(smem);
    int tid = threadIdx.x;
    int wid = tid >> 5, lane = tid & 31;
    int G = gridDim.x;
    int t0 = blockIdx.x;
    int ntb = (NTILES - t0 + G - 1) / G;
    int gw_total = ntb * 8;

    float* sAS = (float*)(smem + SAS_OFF);
    float* sAD = (float*)(smem + SAD_OFF);
    float* sAVS = (float*)(smem + SAVS_OFF);
    float* sAVD = (float*)(smem + SAVD_OFF);

    // ---- producer-independent preamble ----
    if (tid < 128) {
        sAVS[tid] = avs[tid];
        sAVD[tid] = avd[tid];
        sAS[tid] = 0.f; sAD[tid] = 0.f;
    }
    {
        __nv_bfloat16* sB = (__nv_bfloat16*)(smem + SB_OFF);
        for (int i = tid; i < HH * HH; i += 256) {
            int k = i >> 7, n = i & 127;
            float w = Wl[i];
            __nv_bfloat16 hi = __float2bfloat16_rn(w);
            __nv_bfloat16 lo = __float2bfloat16_rn(w - __bfloat162float(hi));
            sB[n * ASTRIDE + k] = hi;
            sB[n * ASTRIDE + 128 + k] = lo;
        }
    }

    cudaGridDependencySynchronize();

    if (donorm && tid < 128) {
        float invN = 1.0f / (float)NN;
        float mean = __ldcg(&g_colsum[slot][tid]) * invN;
        float ex2 = __ldcg(&g_colsq[slot][tid]) * invN;
        float s = gnms[tid];
        float var = ex2 - 2.f * s * mean * mean + s * s * mean * mean;
        float scv = gnw[tid] * rsqrtf(var + EPSN);
        ((float*)(smem + SSC_OFF))[tid] = scv;
        ((float*)(smem + SOF_OFF))[tid] = gnb[tid] - mean * s * scv;
    }
    __syncthreads();

    prefetch_wave(X, t0, G, 0, sbase, tid);
    prefetch_wave(X, t0, G, 1, sbase, tid);
    for (int w = 0; w < 8; w++) {
        if (w + 1 >= gw_total) { CPA_WAIT0(); } else { CPA_WAITG1(); }
        convert_wave(smem, 0, w, donorm, tid);
        if (w + 2 < gw_total) prefetch_wave(X, t0, G, w + 2, sbase, tid);
    }
    __syncthreads();

    int m0 = (wid >> 1) << 5;
    int n0 = (wid & 1) << 6;
    int arow = m0 + (lane & 7) + ((lane >> 3) & 1) * 8;
    uint32_t aBase = sbase + (arow * ASTRIDE + ((lane >> 4) & 1) * 8) * 2;
    int brow = n0 + (lane & 7) + ((lane >> 4) & 1) * 8;
    uint32_t bAddr = sbase + SB_OFF + (brow * ASTRIDE + ((lane >> 3) & 1) * 8) * 2;
    int qrow = lane >> 2;
    int qcol = (lane & 3) << 1;

    int p = 0;
    for (int i = 0; ; i++) {
        int t = t0 + i * G;
        int row0 = t << 7;
        int nrows = NN - row0; if (nrows > 128) nrows = 128;
        int have_next = (i + 1 < ntb);
        uint32_t aAddr = aBase + p * SA_BYTES;
        int dstoff = (p ^ 1) * SA_BYTES;
        float* sASp = sAS + p * 128;
        float* sADp = sAD + p * 128;

        float acc[2][8][4];
        #pragma unroll
        for (int mb = 0; mb < 2; mb++)
            #pragma unroll
            for (int nb = 0; nb < 8; nb++)
                #pragma unroll
                for (int j = 0; j < 4; j++) acc[mb][nb][j] = 0.f;

        for (int w = 0; w < 8; w++) {
            if (have_next) {
                int g = (i + 1) * 8 + w;
                if (g + 1 >= gw_total) { CPA_WAIT0(); } else { CPA_WAITG1(); }
                convert_wave(smem, dstoff, g, donorm, tid);
                if (g + 2 < gw_total) prefetch_wave(X, t0, G, g + 2, sbase, tid);
                if (w == 0 && tid < 128) {
                    sAS[(p ^ 1) * 128 + tid] = 0.f;
                    sAD[(p ^ 1) * 128 + tid] = 0.f;
                }
            }
            int kofs = w * 16;
            uint32_t ah[2][4], al[2][4];
            ldm_x4(ah[0], aAddr + kofs * 2);
            ldm_x4(ah[1], aAddr + kofs * 2 + 16 * ASTRIDE * 2);
            ldm_x4(al[0], aAddr + (kofs + 128) * 2);
            ldm_x4(al[1], aAddr + (kofs + 128) * 2 + 16 * ASTRIDE * 2);
            #pragma unroll
            for (int nbp = 0; nbp < 4; nbp++) {
                uint32_t bh[4], bl[4];
                ldm_x4(bh, bAddr + kofs * 2 + nbp * 16 * ASTRIDE * 2);
                ldm_x4(bl, bAddr + (kofs + 128) * 2 + nbp * 16 * ASTRIDE * 2);
                #pragma unroll
                for (int mb = 0; mb < 2; mb++) {
                    mma16816(acc[mb][2 * nbp],     ah[mb], &bh[0]);
                    mma16816(acc[mb][2 * nbp + 1], ah[mb], &bh[2]);
                    mma16816(acc[mb][2 * nbp],     al[mb], &bh[0]);
                    mma16816(acc[mb][2 * nbp + 1], al[mb], &bh[2]);
                    mma16816(acc[mb][2 * nbp],     ah[mb], &bl[0]);
                    mma16816(acc[mb][2 * nbp + 1], ah[mb], &bl[2]);
                }
            }
        }
        __syncthreads();

        #pragma unroll
        for (int mb = 0; mb < 2; mb++) {
            int rlo = m0 + mb * 16 + qrow;
            int rhi = rlo + 8;
            float as_lo = 0.f, ad_lo = 0.f, as_hi = 0.f, ad_hi = 0.f;
            #pragma unroll
            for (int nb = 0; nb < 8; nb++) {
                int col = n0 + nb * 8 + qcol;
                float c0 = acc[mb][nb][0], c1 = acc[mb][nb][1];
                float c2 = acc[mb][nb][2], c3 = acc[mb][nb][3];
                float s0 = sAVS[col], s1 = sAVS[col + 1];
                float d0 = sAVD[col], d1 = sAVD[col + 1];
                as_lo += c0 * s0 + c1 * s1;  ad_lo += c0 * d0 + c1 * d1;
                as_hi += c2 * s0 + c3 * s1;  ad_hi += c2 * d0 + c3 * d1;
                if (rlo < nrows) {
                    float2* pp = (float2*)(Y + (long long)(row0 + rlo) * HH + col);
                    *pp = make_float2(c0, c1);
                }
                if (rhi < nrows) {
                    float2* pp = (float2*)(Y + (long long)(row0 + rhi) * HH + col);
                    *pp = make_float2(c2, c3);
                }
            }
            #pragma unroll
            for (int o = 1; o < 4; o <<= 1) {
                as_lo += __shfl_xor_sync(0xFFFFFFFFu, as_lo, o);
                ad_lo += __shfl_xor_sync(0xFFFFFFFFu, ad_lo, o);
                as_hi += __shfl_xor_sync(0xFFFFFFFFu, as_hi, o);
                ad_hi += __shfl_xor_sync(0xFFFFFFFFu, ad_hi, o);
            }
            if ((lane & 3) == 0) {
                atomicAdd(&sASp[rlo], as_lo); atomicAdd(&sADp[rlo], ad_lo);
                atomicAdd(&sASp[rhi], as_hi); atomicAdd(&sADp[rhi], ad_hi);
            }
        }
        __syncthreads();
        if (tid < nrows) {
            int r = row0 + tid;
            g_as[r] = sASp[tid]; g_ad[r] = sADp[tid];
        }
        if (!have_next) break;
        p ^= 1;
    }
}

// ---------------- GAT aggregation: PDL, batched phase-1, fused stats/pool ----
__global__ void __launch_bounds__(256)
k_gat_agg(const float* __restrict__ hW, float* __restrict__ hout,
          const float* __restrict__ bias, int mode, int slot) {
    __shared__ float s_sum[HH], s_sq[HH];
    __shared__ int2 s_sa[8][NPW][32];
    int tid = threadIdx.x;
    int wid = tid >> 5, lane = tid & 31;
    if (mode == 1 && tid < HH) { s_sum[tid] = 0.f; s_sq[tid] = 0.f; }
    __syncthreads();

    float4 bb = ((const float4*)bias)[lane];
    int nbase = (blockIdx.x * 8 + wid) * NPW;

    int degs[NPW], rss[NPW], fd[NPW];
    #pragma unroll
    for (int n = 0; n < NPW; n++) {
        int node = nbase + n;
        int val = node < NN;
        rss[n] = val ? g_rowstart[node] : 0;
        int re = val ? g_rowstart[node + 1] : 0;
        degs[n] = re - rss[n];
        fd[n] = (degs[n] <= 32) ? degs[n] : 0;
    }
    int msrc[NPW];
    #pragma unroll
    for (int n = 0; n < NPW; n++)
        msrc[n] = (lane < fd[n]) ? g_ssrc[rss[n] + lane] : 0;

    cudaGridDependencySynchronize();

    float adv[NPW];
    #pragma unroll
    for (int n = 0; n < NPW; n++)
        adv[n] = (nbase + n < NN) ? g_ad[nbase + n] : 0.f;
    float exv[NPW];
    #pragma unroll
    for (int n = 0; n < NPW; n++)
        exv[n] = (lane < fd[n]) ? __expf(lrelu(g_as[msrc[n]] + adv[n], 0.2f)) : 0.f;
    float sv[NPW];
    #pragma unroll
    for (int n = 0; n < NPW; n++) sv[n] = exv[n];
    #pragma unroll
    for (int o = 16; o; o >>= 1) {
        #pragma unroll
        for (int n = 0; n < NPW; n++)
            sv[n] += __shfl_xor_sync(0xFFFFFFFFu, sv[n], o);
    }
    #pragma unroll
    for (int n = 0; n < NPW; n++)
        s_sa[wid][n][lane] = make_int2(msrc[n],
                                       __float_as_int(exv[n] / (sv[n] + 1e-16f)));
    __syncwarp();

    float4 acc[NPW];
    #pragma unroll
    for (int n = 0; n < NPW; n++) acc[n] = bb;
    int dmax = 0;
    #pragma unroll
    for (int n = 0; n < NPW; n++) dmax = max(dmax, fd[n]);
    for (int j = 0; j < dmax; j++) {
        #pragma unroll
        for (int n = 0; n < NPW; n++) {
            if (j < fd[n]) {
                int2 sa = s_sa[wid][n][j];
                float al = __int_as_float(sa.y);
                float4 v = ((const float4*)(hW + (long long)sa.x * HH))[lane];
                acc[n].x += al * v.x; acc[n].y += al * v.y;
                acc[n].z += al * v.z; acc[n].w += al * v.w;
            }
        }
    }
    __syncwarp();
    #pragma unroll
    for (int n = 0; n < NPW; n++) {
        if (degs[n] > 32) {
            int rs = rss[n], re = rss[n] + degs[n];
            float m = -1e30f, s = 0.f;
            for (int i = rs + lane; i < re; i += 32) {
                int src = g_ssrc[i];
                float x = lrelu(g_as[src] + adv[n], 0.2f);
                if (x > m) { s = s * __expf(m - x) + 1.f; m = x; }
                else       { s += __expf(x - m); }
            }
            #pragma unroll
            for (int o = 16; o; o >>= 1) {
                float om = __shfl_xor_sync(0xFFFFFFFFu, m, o);
                float os = __shfl_xor_sync(0xFFFFFFFFu, s, o);
                float nm = fmaxf(m, om);
                s = s * __expf(m - nm) + os * __expf(om - nm);
                m = nm;
            }
            float inv = 1.f / (s + 1e-16f);
            for (int i = rs; i < re; ++i) {
                int src = g_ssrc[i];
                float alpha = __expf(lrelu(g_as[src] + adv[n], 0.2f) - m) * inv;
                float4 v = ((const float4*)(hW + (long long)src * HH))[lane];
                acc[n].x += alpha * v.x; acc[n].y += alpha * v.y;
                acc[n].z += alpha * v.z; acc[n].w += alpha * v.w;
            }
        }
    }

    float4 cs = make_float4(0.f, 0.f, 0.f, 0.f);
    float4 cq = make_float4(0.f, 0.f, 0.f, 0.f);
    float4 pacc = make_float4(0.f, 0.f, 0.f, 0.f);
    int curb = -1;
    #pragma unroll
    for (int n = 0; n < NPW; n++) {
        int node = nbase + n;
        if (node >= NN) break;
        float4 a = acc[n];
        if (mode == 2) {
            int b = g_batch[node];
            if (b != curb) {
                if (curb >= 0) red4(&g_pool[curb * HH + (lane << 2)], pacc);
                curb = b;
                pacc = make_float4(0.f, 0.f, 0.f, 0.f);
            }
            pacc.x += a.x; pacc.y += a.y; pacc.z += a.z; pacc.w += a.w;
        } else {
            ((float4*)(hout + (long long)node * HH))[lane] = a;
            if (mode == 1) {
                cs.x += a.x; cs.y += a.y; cs.z += a.z; cs.w += a.w;
                cq.x += a.x * a.x; cq.y += a.y * a.y;
                cq.z += a.z * a.z; cq.w += a.w * a.w;
            }
        }
    }

    if (mode == 2) {
        if (curb >= 0) red4(&g_pool[curb * HH + (lane << 2)], pacc);
    } else if (mode == 1) {
        int c0 = lane << 2;
        atomicAdd(&s_sum[c0],     cs.x); atomicAdd(&s_sum[c0 + 1], cs.y);
        atomicAdd(&s_sum[c0 + 2], cs.z); atomicAdd(&s_sum[c0 + 3], cs.w);
        atomicAdd(&s_sq[c0],      cq.x); atomicAdd(&s_sq[c0 + 1],  cq.y);
        atomicAdd(&s_sq[c0 + 2],  cq.z); atomicAdd(&s_sq[c0 + 3],  cq.w);
        __syncthreads();
        if (tid < HH) {
            atomicAdd(&g_colsum[slot][tid], s_sum[tid]);
            atomicAdd(&g_colsq[slot][tid], s_sq[tid]);
        }
    }
}

// ---------------- fused MLP (PDL) ---------------------------------------------
__global__ void k_mlp(const float* __restrict__ W1, const float* __restrict__ b1,
                      const float* __restrict__ W2, const float* __restrict__ b2,
                      float* __restrict__ out) {
    __shared__ float sp[HH], sz[HH];
    int g = blockIdx.x, c = threadIdx.x;
    cudaGridDependencySynchronize();
    sp[c] = g_pool[g * HH + c];
    __syncthreads();
    float a1 = b1[c];
    #pragma unroll 4
    for (int k = 0; k < HH; k++) a1 += sp[k] * W1[k * HH + c];
    sz[c] = lrelu(a1, 0.01f);
    __syncthreads();
    if (c < AA) {
        float a2 = b2[c];
        #pragma unroll 4
        for (int k = 0; k < HH; k++) a2 += sz[k] * W2[k * AA + c];
        out[g * AA + c] = a2;
    }
}

// ---------------- launcher ---------------------------------------------------
static cudaStream_t get_side_stream() {
    static cudaStream_t s = [] {
        cudaStream_t t;
        cudaStreamCreateWithFlags(&t, cudaStreamNonBlocking);
        return t;
    }();
    return s;
}
static cudaEvent_t get_event(int which) {
    static cudaEvent_t e[2] = { [] { cudaEvent_t t;
                                     cudaEventCreateWithFlags(&t, cudaEventDisableTiming);
                                     return t; }(),
                                [] { cudaEvent_t t;
                                     cudaEventCreateWithFlags(&t, cudaEventDisableTiming);
                                     return t; }() };
    return e[which];
}

template <typename F, typename... Args>
static void launch_pdl(F f, dim3 grid, dim3 block, size_t smem, cudaStream_t st,
                       Args... args) {
    cudaLaunchConfig_t cfg = {};
    cfg.gridDim = grid;
    cfg.blockDim = block;
    cfg.dynamicSmemBytes = smem;
    cfg.stream = st;
    cudaLaunchAttribute attr[1];
    attr[0].id = cudaLaunchAttributeProgrammaticStreamSerialization;
    attr[0].val.programmaticStreamSerializationAllowed = 1;
    cfg.attrs = attr;
    cfg.numAttrs = 1;
    cudaLaunchKernelEx(&cfg, f, args...);
}

extern "C" void kernel_launch(void* const* d_in, const int* in_sizes, int n_in,
                              void* d_out, int out_size) {
    const float* x        = (const float*)d_in[0];
    const void*  e_raw    = d_in[1];
    const void*  b_raw    = d_in[2];
    const float* Ws       = (const float*)d_in[3];
    const float* att_src  = (const float*)d_in[4];
    const float* att_dst  = (const float*)d_in[5];
    const float* conv_bias= (const float*)d_in[6];
    const float* gn_w     = (const float*)d_in[7];
    const float* gn_b     = (const float*)d_in[8];
    const float* gn_ms    = (const float*)d_in[9];
    const float* W1       = (const float*)d_in[10];
    const float* b1       = (const float*)d_in[11];
    const float* W2       = (const float*)d_in[12];
    const float* b2       = (const float*)d_in[13];

    float* bufA; float* bufB;
    cudaGetSymbolAddress((void**)&bufA, g_bufA);
    cudaGetSymbolAddress((void**)&bufB, g_bufB);

    cudaFuncSetAttribute(k_gemm_mma, cudaFuncAttributeMaxDynamicSharedMemorySize, GEMM_SMEM);

    cudaStream_t s2 = get_side_stream();
    cudaEvent_t evF = get_event(0), evJ = get_event(1);

    const int eg = (EE + 255) / 256;
    const int ng = (NN + 255) / 256;
    const int NB = (NN + 1023) / 1024;
    const int agg_grid = (NN + 8 * NPW - 1) / (8 * NPW);

    cudaEventRecord(evF, 0);
    cudaStreamWaitEvent(s2, evF, 0);
    k_cvt<<<eg, 256, 0, s2>>>(e_raw, b_raw);
    k_scan1<<<NB, 256, 0, s2>>>();
    k_scan23<<<ng, 256, 0, s2>>>();
    k_fill<<<eg, 256, 0, s2>>>();
    cudaEventRecord(evJ, s2);

    k_gemm_mma<<<148, 256, GEMM_SMEM>>>(x, Ws, bufA, att_src, att_dst, 0, 0,
                                        gn_w, gn_b, gn_ms);
    cudaStreamWaitEvent(0, evJ, 0);

    for (int l = 0; l < LL; l++) {
        if (l > 0) {
            launch_pdl(k_gemm_mma, dim3(148), dim3(256), (size_t)GEMM_SMEM,
                       (cudaStream_t)0,
                       (const float*)bufB, Ws + l * HH * HH, bufA,
                       att_src + l * HH, att_dst + l * HH,
                       1, l - 1,
                       gn_w + (l - 1) * HH, gn_b + (l - 1) * HH,
                       gn_ms + (l - 1) * HH);
        }
        int mode = (l < LL - 1) ? 1 : 2;
        launch_pdl(k_gat_agg, dim3(agg_grid), dim3(256), (size_t)0,
                   (cudaStream_t)0,
                   (const float*)bufA, bufB, conv_bias + l * HH, mode, l);
    }

    launch_pdl(k_mlp, dim3(GG), dim3(128), (size_t)0, (cudaStream_t)0,
               W1, b1, W2, b2, (float*)d_out);
}